// round 14
// baseline (speedup 1.0000x reference)
#include <cuda_runtime.h>
#include <cuda_fp16.h>
#include <cstdint>
#include <math.h>

#define Tn 4096
#define Hd 2048
#define Id 8192
#define NE 8
#define NA (2*Tn)
#define MAXT 80

// ---------------- device scratch (no allocs allowed) ----------------
__device__ int    g_cnt[NE];
__device__ int    g_cur[NE];
__device__ int    g_tileE[MAXT], g_tileRow0[MAXT], g_tileRows[MAXT];
__device__ int    g_ntiles;
__device__ int    g_topi[Tn*2];
__device__ float  g_topw[Tn*2];
__device__ int    g_tok[NA];
__device__ float  g_w[NA];
__device__ float  g_logits_scratch[Tn*NE];
__device__ __half g_h_h[(size_t)NA*Id];              // 134 MiB intermediate (fp16)
__device__ __half g_wg_h[(size_t)NE*Id*Hd];          // fp16 weights
__device__ __half g_wu_h[(size_t)NE*Id*Hd];
__device__ __half g_wd_h[(size_t)NE*Hd*Id];
__device__ __half g_hid_h[(size_t)Tn*Hd];

// ---------------- helpers ----------------
__device__ __forceinline__ uint32_t smem_u32(const void* p){
    uint32_t a; asm("{ .reg .u64 t; cvta.to.shared.u64 t, %1; cvt.u32.u64 %0, t; }" : "=r"(a) : "l"(p));
    return a;
}
__device__ __forceinline__ void cp16u(uint32_t sa, const void* g){
    asm volatile("cp.async.cg.shared.global [%0], [%1], 16;\n" :: "r"(sa), "l"(g));
}
#define CP_COMMIT() asm volatile("cp.async.commit_group;\n")
#define CP_WAIT1()  asm volatile("cp.async.wait_group 1;\n")
#define CP_WAIT0()  asm volatile("cp.async.wait_group 0;\n")

__device__ __forceinline__ void ldm_x4(uint32_t& r0, uint32_t& r1, uint32_t& r2, uint32_t& r3, uint32_t addr){
    asm volatile("ldmatrix.sync.aligned.m8n8.x4.shared.b16 {%0,%1,%2,%3}, [%4];\n"
        : "=r"(r0), "=r"(r1), "=r"(r2), "=r"(r3) : "r"(addr));
}
__device__ __forceinline__ void mma_f16(float* c, const uint32_t* a, uint32_t b0, uint32_t b1){
    asm volatile(
      "mma.sync.aligned.m16n8k16.row.col.f32.f16.f16.f32 "
      "{%0,%1,%2,%3}, {%4,%5,%6,%7}, {%8,%9}, {%0,%1,%2,%3};\n"
      : "+f"(c[0]), "+f"(c[1]), "+f"(c[2]), "+f"(c[3])
      : "r"(a[0]), "r"(a[1]), "r"(a[2]), "r"(a[3]), "r"(b0), "r"(b1));
}
__device__ __forceinline__ float gelu_exact(float x){
    return 0.5f * x * (1.0f + erff(x * 0.70710678118654752440f));
}
// swizzle for 128B rows: byte offset within tile
__device__ __forceinline__ uint32_t sw128(uint32_t off){ return off ^ ((off >> 3) & 0x70); }

// ---------------- small kernels ----------------
__global__ void zero_kernel(){ if (threadIdx.x < NE) g_cnt[threadIdx.x] = 0; }

// convert rows [r0, r0+nrows) of each expert of a (NE, Id, Hd) tensor
__global__ void cvt16_part_kernel(const float4* __restrict__ s, uint4* __restrict__ d,
                                  int r0, int nrows){
    const int chunk8 = nrows * (Hd/8);           // uint4s per expert chunk
    const int n8 = NE * chunk8;
    const int base8 = r0 * (Hd/8);
    int i = blockIdx.x * blockDim.x + threadIdx.x;
    int st = gridDim.x * blockDim.x;
    for (; i < n8; i += st){
        int e = i / chunk8, j = i - e * chunk8;
        size_t idx = (size_t)e * (Id*Hd/8) + base8 + j;
        float4 a = s[2*idx], b = s[2*idx+1];
        union { __half2 h[4]; uint4 u; } pk;
        pk.h[0] = __floats2half2_rn(a.x, a.y);
        pk.h[1] = __floats2half2_rn(a.z, a.w);
        pk.h[2] = __floats2half2_rn(b.x, b.y);
        pk.h[3] = __floats2half2_rn(b.z, b.w);
        d[idx] = pk.u;
    }
}

// convert column chunk [c08*8, (c08+nc8)*8) of every row of a (nrows, rowLen8*8) tensor
__global__ void cvt16_colpart_kernel(const float4* __restrict__ s, uint4* __restrict__ d,
                                     int nrows, int rowLen8, int c08, int nc8){
    const int n8 = nrows * nc8;
    int i = blockIdx.x * blockDim.x + threadIdx.x;
    int st = gridDim.x * blockDim.x;
    for (; i < n8; i += st){
        int r = i / nc8, j = i - r * nc8;
        size_t idx = (size_t)r * rowLen8 + c08 + j;
        float4 a = s[2*idx], b = s[2*idx+1];
        union { __half2 h[4]; uint4 u; } pk;
        pk.h[0] = __floats2half2_rn(a.x, a.y);
        pk.h[1] = __floats2half2_rn(a.z, a.w);
        pk.h[2] = __floats2half2_rn(b.x, b.y);
        pk.h[3] = __floats2half2_rn(b.z, b.w);
        d[idx] = pk.u;
    }
}

// router: logits + top2 + also emits fp16 copy of hidden (saves a separate cvt pass)
__global__ void router_kernel(const float* __restrict__ x,
                              const float* __restrict__ gw,
                              float* __restrict__ logits_out)
{
    int warp = threadIdx.x >> 5, lane = threadIdx.x & 31;
    int t = blockIdx.x * 8 + warp;
    if (t >= Tn) return;
    const float* xr = x + (size_t)t * Hd;
    __half* hr = g_hid_h + (size_t)t * Hd;
    float l[NE];
    #pragma unroll
    for (int e = 0; e < NE; e++){
        float acc = 0.f;
        const float* w = gw + e * Hd;
        if (e == 0){
            for (int k = lane; k < Hd; k += 32){
                float v = xr[k];
                acc += v * w[k];
                hr[k] = __float2half_rn(v);
            }
        } else {
            for (int k = lane; k < Hd; k += 32) acc += xr[k] * w[k];
        }
        #pragma unroll
        for (int o = 16; o; o >>= 1) acc += __shfl_xor_sync(0xffffffffu, acc, o);
        l[e] = acc;
    }
    if (lane == 0){
        #pragma unroll
        for (int e = 0; e < NE; e++) logits_out[t*NE + e] = l[e];
        float m = l[0];
        #pragma unroll
        for (int e = 1; e < NE; e++) m = fmaxf(m, l[e]);
        float p[NE]; float s = 0.f;
        #pragma unroll
        for (int e = 0; e < NE; e++){ p[e] = expf(l[e] - m); s += p[e]; }
        float inv = 1.f / s;
        #pragma unroll
        for (int e = 0; e < NE; e++) p[e] *= inv;
        int i1 = 0;
        #pragma unroll
        for (int e = 1; e < NE; e++) if (p[e] > p[i1]) i1 = e;
        int i2 = (i1 == 0) ? 1 : 0;
        #pragma unroll
        for (int e = 0; e < NE; e++){ if (e == i1) continue; if (p[e] > p[i2]) i2 = e; }
        g_topi[t*2+0] = i1; g_topi[t*2+1] = i2;
        g_topw[t*2+0] = p[i1]; g_topw[t*2+1] = p[i2];
        atomicAdd(&g_cnt[i1], 1); atomicAdd(&g_cnt[i2], 1);
    }
}

__global__ void prefix_kernel(){
    int off = 0, nt = 0;
    for (int e = 0; e < NE; e++){
        g_cur[e] = off;
        int c = g_cnt[e];
        int tiles = (c + 127) >> 7;
        for (int j = 0; j < tiles; j++){
            g_tileE[nt] = e;
            g_tileRow0[nt] = off + j*128;
            g_tileRows[nt] = min(128, c - j*128);
            nt++;
        }
        off += c;
    }
    g_ntiles = nt;
}

__global__ void scatter_kernel(){
    int t = blockIdx.x * blockDim.x + threadIdx.x;
    if (t >= Tn) return;
    #pragma unroll
    for (int s = 0; s < 2; s++){
        int e = g_topi[t*2+s];
        int p = atomicAdd(&g_cur[e], 1);
        g_tok[p] = t;
        g_w[p]   = g_topw[t*2+s];
    }
}

// ========== GEMM1: fp16 mma.sync, CTA 128(M)x64(N) dual-mat, 128 thr, warp 64x32, BK=64 ==========
// stage layout (32KB): A @0 (128x64h=16KB), Bg @16384 (8KB), Bu @24576 (8KB); 3 stages, 2 CTA/SM
#define G1_STAGE 32768
#define SMEM1 (3*G1_STAGE)

__global__ void __launch_bounds__(128, 2) gemm1_kernel(int colOffset)
{
    extern __shared__ char smem[];
    __shared__ int toks[128];
    uint32_t sb = smem_u32(smem);
    int bt = blockIdx.x;                       // row tile (x fastest: weight slices shared in L2)
    if (bt >= g_ntiles) return;
    int e = g_tileE[bt], row0 = g_tileRow0[bt], rows = g_tileRows[bt];
    int colBase = colOffset + blockIdx.y * 64;
    int tid = threadIdx.x, wid = tid >> 5, lane = tid & 31;

    toks[tid] = g_tok[row0 + (tid < rows ? tid : 0)];
    __syncthreads();

    const __half* Gb = g_wg_h + ((size_t)e*Id + colBase) * Hd;
    const __half* Ub = g_wu_h + ((size_t)e*Id + colBase) * Hd;

    auto load_stage = [&](int sidx, int k0){
        uint32_t base = sb + sidx*G1_STAGE;
        #pragma unroll
        for (int i = 0; i < 8; i++){
            int idx = tid + i*128; int r = idx >> 3, c = idx & 7;
            uint32_t off = (uint32_t)(r*128 + c*16);
            cp16u(base + sw128(off), g_hid_h + (size_t)toks[r]*Hd + k0 + c*8);
        }
        #pragma unroll
        for (int i = 0; i < 4; i++){
            int idx = tid + i*128; int r = idx >> 3, c = idx & 7;   // r in [0,64)
            uint32_t off = (uint32_t)(r*128 + c*16);
            uint32_t sw = sw128(off);
            cp16u(base + 16384 + sw, Gb + (size_t)r*Hd + k0 + c*8);
            cp16u(base + 24576 + sw, Ub + (size_t)r*Hd + k0 + c*8);
        }
        CP_COMMIT();
    };

    int wm = wid & 1, wn = wid >> 1;   // 2x2 warps over 128x64 (warp tile 64x32)
    float cg[4][4][4], cu[4][4][4];
    #pragma unroll
    for (int a = 0; a < 4; a++)
      #pragma unroll
      for (int b = 0; b < 4; b++)
        #pragma unroll
        for (int c = 0; c < 4; c++){ cg[a][b][c] = 0.f; cu[a][b][c] = 0.f; }

    int a_row = (lane & 15);
    int a_hi  = (lane >> 4) * 16;
    int b_row = (lane & 7) + ((lane >> 4) ? 8 : 0);
    int b_hi  = ((lane >> 3) & 1) * 16;

    const int KT = Hd / 64;    // 32
    load_stage(0, 0);
    load_stage(1, 64);

    int sidx = 0;                       // stage of iter k (mod 3)
    for (int k = 0; k < KT; k++){
        if (k + 1 < KT) { CP_WAIT1(); } else { CP_WAIT0(); }
        __syncthreads();
        if (k + 2 < KT){
            int ns = sidx + 2; if (ns >= 3) ns -= 3;
            load_stage(ns, (k+2)*64);
        }
        uint32_t base = sb + sidx*G1_STAGE;
        #pragma unroll
        for (int s = 0; s < 4; s++){
            uint32_t af[4][4];
            #pragma unroll
            for (int mi = 0; mi < 4; mi++){
                int r = wm*64 + mi*16 + a_row;
                ldm_x4(af[mi][0], af[mi][1], af[mi][2], af[mi][3],
                       base + sw128((uint32_t)(r*128 + s*32 + a_hi)));
            }
            #pragma unroll
            for (int nj = 0; nj < 2; nj++){
                int r = wn*32 + nj*16 + b_row;
                uint32_t off = sw128((uint32_t)(r*128 + s*32 + b_hi));
                uint32_t bg0,bg1,bg2,bg3, bu0,bu1,bu2,bu3;
                ldm_x4(bg0,bg1,bg2,bg3, base + 16384 + off);
                ldm_x4(bu0,bu1,bu2,bu3, base + 24576 + off);
                #pragma unroll
                for (int mi = 0; mi < 4; mi++){
                    mma_f16(cg[mi][nj*2+0], af[mi], bg0, bg1);
                    mma_f16(cg[mi][nj*2+1], af[mi], bg2, bg3);
                    mma_f16(cu[mi][nj*2+0], af[mi], bu0, bu1);
                    mma_f16(cu[mi][nj*2+1], af[mi], bu2, bu3);
                }
            }
        }
        sidx++; if (sidx >= 3) sidx = 0;
    }

    // epilogue: h = gelu(g)*u -> fp16 (intra-warp: each warp owns g AND u for its cols)
    int grp = lane >> 2, tg = lane & 3;
    #pragma unroll
    for (int mi = 0; mi < 4; mi++)
      #pragma unroll
      for (int nf = 0; nf < 4; nf++){
        int r0 = wm*64 + mi*16 + grp;
        int gc = colBase + wn*32 + nf*8 + tg*2;
        if (r0 < rows){
            size_t o = (size_t)(row0 + r0)*Id + gc;
            *(__half2*)(g_h_h + o) = __floats2half2_rn(
                gelu_exact(cg[mi][nf][0]) * cu[mi][nf][0],
                gelu_exact(cg[mi][nf][1]) * cu[mi][nf][1]);
        }
        if (r0 + 8 < rows){
            size_t o = (size_t)(row0 + r0 + 8)*Id + gc;
            *(__half2*)(g_h_h + o) = __floats2half2_rn(
                gelu_exact(cg[mi][nf][2]) * cu[mi][nf][2],
                gelu_exact(cg[mi][nf][3]) * cu[mi][nf][3]);
        }
      }
}

// ================== GEMM2: fp16 mma.sync, CTA 128x128, 128 threads, warp tile 64x64 ==================
// grid: (Hd/128=16 cols = x fastest, rowtiles = y); kOffset selects the K chunk
// stage layout (32KB): A @0 (16KB), B @16384 (16KB); 3 stages, 2 CTA/SM (128 thr each)
#define G2_STAGE 32768
#define SMEM2 (3*G2_STAGE)
#define G2_KCHUNK 2048

__global__ void __launch_bounds__(128, 2) gemm2_kernel(float* __restrict__ outp, int kOffset)
{
    extern __shared__ char smem[];
    __shared__ int   toks[128];
    __shared__ float ws[128];
    uint32_t sb = smem_u32(smem);
    int bt = blockIdx.y;                       // row tile
    if (bt >= g_ntiles) return;
    int e = g_tileE[bt], row0 = g_tileRow0[bt], rows = g_tileRows[bt];
    int colBase = blockIdx.x * 128;            // column tile (x fastest)
    int tid = threadIdx.x, wid = tid >> 5, lane = tid & 31;

    {
        int r = tid < rows ? tid : 0;
        toks[tid] = g_tok[row0 + r];
        ws[tid]   = g_w[row0 + r];
    }
    __syncthreads();

    const __half* Bb = g_wd_h + ((size_t)e*Hd + colBase) * Id;

    auto load_stage = [&](int sidx, int k0){
        uint32_t base = sb + sidx*G2_STAGE;
        #pragma unroll
        for (int i = 0; i < 8; i++){
            int idx = tid + i*128; int r = idx >> 3, c = idx & 7;
            int ar = row0 + (r < rows ? r : 0);
            uint32_t off = (uint32_t)(r*128 + c*16);
            cp16u(base + sw128(off), g_h_h + (size_t)ar*Id + k0 + c*8);
        }
        #pragma unroll
        for (int i = 0; i < 8; i++){
            int idx = tid + i*128; int r = idx >> 3, c = idx & 7;
            uint32_t off = (uint32_t)(r*128 + c*16);
            cp16u(base + 16384 + sw128(off), Bb + (size_t)r*Id + k0 + c*8);
        }
        CP_COMMIT();
    };

    int wm = wid & 1, wn = wid >> 1;   // 2x2 warps over 128x128 (warp 64x64)
    float cc[4][8][4];
    #pragma unroll
    for (int a = 0; a < 4; a++)
      #pragma unroll
      for (int b = 0; b < 8; b++)
        #pragma unroll
        for (int c = 0; c < 4; c++) cc[a][b][c] = 0.f;

    int a_row = (lane & 15);
    int a_hi  = (lane >> 4) * 16;
    int b_row = (lane & 7) + ((lane >> 4) ? 8 : 0);
    int b_hi  = ((lane >> 3) & 1) * 16;

    const int KT = G2_KCHUNK / 64;    // 32
    load_stage(0, kOffset);
    load_stage(1, kOffset + 64);

    int sidx = 0;
    for (int k = 0; k < KT; k++){
        if (k + 1 < KT) { CP_WAIT1(); } else { CP_WAIT0(); }
        __syncthreads();
        if (k + 2 < KT){
            int ns = sidx + 2; if (ns >= 3) ns -= 3;
            load_stage(ns, kOffset + (k+2)*64);
        }
        uint32_t base = sb + sidx*G2_STAGE;
        #pragma unroll
        for (int s = 0; s < 4; s++){
            uint32_t af[4][4];
            #pragma unroll
            for (int mi = 0; mi < 4; mi++){
                int r = wm*64 + mi*16 + a_row;
                ldm_x4(af[mi][0], af[mi][1], af[mi][2], af[mi][3],
                       base + sw128((uint32_t)(r*128 + s*32 + a_hi)));
            }
            #pragma unroll
            for (int nj = 0; nj < 4; nj++){
                int r = wn*64 + nj*16 + b_row;
                uint32_t b0,b1,b2,b3;
                ldm_x4(b0,b1,b2,b3, base + 16384 + sw128((uint32_t)(r*128 + s*32 + b_hi)));
                #pragma unroll
                for (int mi = 0; mi < 4; mi++){
                    mma_f16(cc[mi][nj*2+0], af[mi], b0, b1);
                    mma_f16(cc[mi][nj*2+1], af[mi], b2, b3);
                }
            }
        }
        sidx++; if (sidx >= 3) sidx = 0;
    }

    // epilogue: out[token] += w * partial (all contributions commute)
    int grp = lane >> 2, tg = lane & 3;
    #pragma unroll
    for (int mi = 0; mi < 4; mi++)
      #pragma unroll
      for (int nf = 0; nf < 8; nf++){
        int r0 = wm*64 + mi*16 + grp;
        int gc = colBase + wn*64 + nf*8 + tg*2;
        if (r0 < rows){
            float w = ws[r0];
            float* o = outp + (size_t)toks[r0]*Hd + gc;
            atomicAdd(o,   w * cc[mi][nf][0]);
            atomicAdd(o+1, w * cc[mi][nf][1]);
        }
        if (r0 + 8 < rows){
            float w = ws[r0+8];
            float* o = outp + (size_t)toks[r0+8]*Hd + gc;
            atomicAdd(o,   w * cc[mi][nf][2]);
            atomicAdd(o+1, w * cc[mi][nf][3]);
        }
      }
}

// ---------------- launch ----------------
extern "C" void kernel_launch(void* const* d_in, const int* in_sizes, int n_in,
                              void* d_out, int out_size)
{
    const float* hidden = (const float*)d_in[0];
    const float* gate_w = (const float*)d_in[1];
    const float* w_gate = (const float*)d_in[2];
    const float* w_up   = (const float*)d_in[3];
    const float* w_down = (const float*)d_in[4];
    float* out = (float*)d_out;

    float* logits_dst;
    if (out_size >= Tn*Hd + Tn*NE) {
        logits_dst = out + (size_t)Tn*Hd;
    } else {
        void* p = nullptr;
        cudaGetSymbolAddress(&p, g_logits_scratch);
        logits_dst = (float*)p;
    }

    void *pwg, *pwu, *pwd;
    cudaGetSymbolAddress(&pwg,  g_wg_h);
    cudaGetSymbolAddress(&pwu,  g_wu_h);
    cudaGetSymbolAddress(&pwd,  g_wd_h);

    // one-time host-side resources (3 side streams — 4 tripped the teardown mem check)
    static cudaStream_t s1 = nullptr, s2 = nullptr, s3 = nullptr;
    static cudaEvent_t evRoot = nullptr, evG2a = nullptr, evG2b = nullptr;
    static cudaEvent_t evQ[4]  = {nullptr,nullptr,nullptr,nullptr};
    static cudaEvent_t evWD[4] = {nullptr,nullptr,nullptr,nullptr};
    static cudaEvent_t evG1[4] = {nullptr,nullptr,nullptr,nullptr};
    static bool inited = false;
    if (!inited){
        cudaStreamCreateWithFlags(&s1, cudaStreamNonBlocking);
        cudaStreamCreateWithFlags(&s2, cudaStreamNonBlocking);
        cudaStreamCreateWithFlags(&s3, cudaStreamNonBlocking);
        cudaEventCreateWithFlags(&evRoot, cudaEventDisableTiming);
        cudaEventCreateWithFlags(&evG2a,  cudaEventDisableTiming);
        cudaEventCreateWithFlags(&evG2b,  cudaEventDisableTiming);
        for (int q = 0; q < 4; q++){
            cudaEventCreateWithFlags(&evQ[q],  cudaEventDisableTiming);
            cudaEventCreateWithFlags(&evWD[q], cudaEventDisableTiming);
            cudaEventCreateWithFlags(&evG1[q], cudaEventDisableTiming);
        }
        cudaFuncSetAttribute(gemm1_kernel, cudaFuncAttributeMaxDynamicSharedMemorySize, SMEM1);
        cudaFuncSetAttribute(gemm2_kernel, cudaFuncAttributeMaxDynamicSharedMemorySize, SMEM2);
        inited = true;
    }

    const int QTR = Id/4;                          // 2048 rows per quarter (per expert)

    // fork: root event on the (capturing) default stream
    zero_kernel<<<1, 32, 0, 0>>>();
    cudaEventRecord(evRoot, 0);
    cudaStreamWaitEvent(s1, evRoot, 0);

    // s1: wg/wu in 4 column-quarters (hidden fp16 produced by the router)
    for (int q = 0; q < 4; q++){
        cvt16_part_kernel<<<2048, 256, 0, s1>>>((const float4*)w_gate, (uint4*)pwg, q*QTR, QTR);
        cvt16_part_kernel<<<2048, 256, 0, s1>>>((const float4*)w_up,   (uint4*)pwu, q*QTR, QTR);
        cudaEventRecord(evQ[q], s1);
    }

    // s2: w_down cvt in K(column)-quarters, AFTER the s1 chain (runs under gemm1)
    cudaStreamWaitEvent(s2, evQ[3], 0);
    for (int q = 0; q < 4; q++){
        cvt16_colpart_kernel<<<2048, 256, 0, s2>>>((const float4*)w_down, (uint4*)pwd,
                                                   NE*Hd, Id/8, q*(G2_KCHUNK/8), G2_KCHUNK/8);
        cudaEventRecord(evWD[q], s2);
    }

    // default stream: routing chain (emits g_hid_h) + output zero
    cudaMemsetAsync(d_out, 0, (size_t)Tn*Hd*sizeof(float), 0);
    router_kernel<<<Tn/8, 256, 0, 0>>>(hidden, gate_w, logits_dst);
    prefix_kernel<<<1, 1, 0, 0>>>();
    scatter_kernel<<<Tn/256, 256, 0, 0>>>();

    // gemm1 in 4 column-quarter chunks, each gated on its cvt pair
    for (int q = 0; q < 4; q++){
        cudaStreamWaitEvent(0, evQ[q], 0);
        gemm1_kernel<<<dim3(72, QTR/64), 128, SMEM1, 0>>>(q*QTR);
        cudaEventRecord(evG1[q], 0);
    }

    // gemm2 K-chunks alternating on s3 / s2 (s2 is free after the wd cvts; chunks commute)
    for (int q = 0; q < 4; q++){
        cudaStream_t sc = (q & 1) ? s2 : s3;
        cudaStreamWaitEvent(sc, evG1[q], 0);
        cudaStreamWaitEvent(sc, evWD[q], 0);
        gemm2_kernel<<<dim3(Hd/128, 72), 128, SMEM2, sc>>>(out, q*G2_KCHUNK);
    }
    cudaEventRecord(evG2a, s3);
    cudaEventRecord(evG2b, s2);

    // join everything back into the capture-origin stream
    cudaStreamWaitEvent(0, evG2a, 0);
    cudaStreamWaitEvent(0, evG2b, 0);
}

// round 15
// speedup vs baseline: 1.0170x; 1.0170x over previous
#include <cuda_runtime.h>
#include <cuda_fp16.h>
#include <cstdint>
#include <math.h>

#define Tn 4096
#define Hd 2048
#define Id 8192
#define NE 8
#define NA (2*Tn)
#define MAXT 80

// ---------------- device scratch (no allocs allowed) ----------------
__device__ int    g_cnt[NE];
__device__ int    g_cur[NE];
__device__ int    g_tileE[MAXT], g_tileRow0[MAXT], g_tileRows[MAXT];
__device__ int    g_ntiles;
__device__ int    g_topi[Tn*2];
__device__ float  g_topw[Tn*2];
__device__ int    g_tok[NA];
__device__ float  g_w[NA];
__device__ float  g_logits_scratch[Tn*NE];
__device__ __half g_h_h[(size_t)NA*Id];              // 134 MiB intermediate (fp16)
__device__ __half g_wg_h[(size_t)NE*Id*Hd];          // fp16 weights
__device__ __half g_wu_h[(size_t)NE*Id*Hd];
__device__ __half g_wd_h[(size_t)NE*Hd*Id];
__device__ __half g_hid_h[(size_t)Tn*Hd];

// ---------------- helpers ----------------
__device__ __forceinline__ uint32_t smem_u32(const void* p){
    uint32_t a; asm("{ .reg .u64 t; cvta.to.shared.u64 t, %1; cvt.u32.u64 %0, t; }" : "=r"(a) : "l"(p));
    return a;
}
__device__ __forceinline__ void cp16u(uint32_t sa, const void* g){
    asm volatile("cp.async.cg.shared.global [%0], [%1], 16;\n" :: "r"(sa), "l"(g));
}
#define CP_COMMIT() asm volatile("cp.async.commit_group;\n")
#define CP_WAIT1()  asm volatile("cp.async.wait_group 1;\n")
#define CP_WAIT0()  asm volatile("cp.async.wait_group 0;\n")

__device__ __forceinline__ void ldm_x4(uint32_t& r0, uint32_t& r1, uint32_t& r2, uint32_t& r3, uint32_t addr){
    asm volatile("ldmatrix.sync.aligned.m8n8.x4.shared.b16 {%0,%1,%2,%3}, [%4];\n"
        : "=r"(r0), "=r"(r1), "=r"(r2), "=r"(r3) : "r"(addr));
}
__device__ __forceinline__ void mma_f16(float* c, const uint32_t* a, uint32_t b0, uint32_t b1){
    asm volatile(
      "mma.sync.aligned.m16n8k16.row.col.f32.f16.f16.f32 "
      "{%0,%1,%2,%3}, {%4,%5,%6,%7}, {%8,%9}, {%0,%1,%2,%3};\n"
      : "+f"(c[0]), "+f"(c[1]), "+f"(c[2]), "+f"(c[3])
      : "r"(a[0]), "r"(a[1]), "r"(a[2]), "r"(a[3]), "r"(b0), "r"(b1));
}
__device__ __forceinline__ float gelu_exact(float x){
    return 0.5f * x * (1.0f + erff(x * 0.70710678118654752440f));
}
// swizzle for 128B rows: byte offset within tile
__device__ __forceinline__ uint32_t sw128(uint32_t off){ return off ^ ((off >> 3) & 0x70); }

// ---------------- small kernels ----------------
__global__ void zero_kernel(){ if (threadIdx.x < NE) g_cnt[threadIdx.x] = 0; }

// convert rows [r0, r0+nrows) of each expert of a (NE, Id, Hd) tensor
__global__ void cvt16_part_kernel(const float4* __restrict__ s, uint4* __restrict__ d,
                                  int r0, int nrows){
    const int chunk8 = nrows * (Hd/8);           // uint4s per expert chunk
    const int n8 = NE * chunk8;
    const int base8 = r0 * (Hd/8);
    int i = blockIdx.x * blockDim.x + threadIdx.x;
    int st = gridDim.x * blockDim.x;
    for (; i < n8; i += st){
        int e = i / chunk8, j = i - e * chunk8;
        size_t idx = (size_t)e * (Id*Hd/8) + base8 + j;
        float4 a = s[2*idx], b = s[2*idx+1];
        union { __half2 h[4]; uint4 u; } pk;
        pk.h[0] = __floats2half2_rn(a.x, a.y);
        pk.h[1] = __floats2half2_rn(a.z, a.w);
        pk.h[2] = __floats2half2_rn(b.x, b.y);
        pk.h[3] = __floats2half2_rn(b.z, b.w);
        d[idx] = pk.u;
    }
}

// convert column chunk [c08*8, (c08+nc8)*8) of every row of a (nrows, rowLen8*8) tensor
__global__ void cvt16_colpart_kernel(const float4* __restrict__ s, uint4* __restrict__ d,
                                     int nrows, int rowLen8, int c08, int nc8){
    const int n8 = nrows * nc8;
    int i = blockIdx.x * blockDim.x + threadIdx.x;
    int st = gridDim.x * blockDim.x;
    for (; i < n8; i += st){
        int r = i / nc8, j = i - r * nc8;
        size_t idx = (size_t)r * rowLen8 + c08 + j;
        float4 a = s[2*idx], b = s[2*idx+1];
        union { __half2 h[4]; uint4 u; } pk;
        pk.h[0] = __floats2half2_rn(a.x, a.y);
        pk.h[1] = __floats2half2_rn(a.z, a.w);
        pk.h[2] = __floats2half2_rn(b.x, b.y);
        pk.h[3] = __floats2half2_rn(b.z, b.w);
        d[idx] = pk.u;
    }
}

// router: logits + top2 + also emits fp16 copy of hidden (saves a separate cvt pass)
__global__ void router_kernel(const float* __restrict__ x,
                              const float* __restrict__ gw,
                              float* __restrict__ logits_out)
{
    int warp = threadIdx.x >> 5, lane = threadIdx.x & 31;
    int t = blockIdx.x * 8 + warp;
    if (t >= Tn) return;
    const float* xr = x + (size_t)t * Hd;
    __half* hr = g_hid_h + (size_t)t * Hd;
    float l[NE];
    #pragma unroll
    for (int e = 0; e < NE; e++){
        float acc = 0.f;
        const float* w = gw + e * Hd;
        if (e == 0){
            for (int k = lane; k < Hd; k += 32){
                float v = xr[k];
                acc += v * w[k];
                hr[k] = __float2half_rn(v);
            }
        } else {
            for (int k = lane; k < Hd; k += 32) acc += xr[k] * w[k];
        }
        #pragma unroll
        for (int o = 16; o; o >>= 1) acc += __shfl_xor_sync(0xffffffffu, acc, o);
        l[e] = acc;
    }
    if (lane == 0){
        #pragma unroll
        for (int e = 0; e < NE; e++) logits_out[t*NE + e] = l[e];
        float m = l[0];
        #pragma unroll
        for (int e = 1; e < NE; e++) m = fmaxf(m, l[e]);
        float p[NE]; float s = 0.f;
        #pragma unroll
        for (int e = 0; e < NE; e++){ p[e] = expf(l[e] - m); s += p[e]; }
        float inv = 1.f / s;
        #pragma unroll
        for (int e = 0; e < NE; e++) p[e] *= inv;
        int i1 = 0;
        #pragma unroll
        for (int e = 1; e < NE; e++) if (p[e] > p[i1]) i1 = e;
        int i2 = (i1 == 0) ? 1 : 0;
        #pragma unroll
        for (int e = 0; e < NE; e++){ if (e == i1) continue; if (p[e] > p[i2]) i2 = e; }
        g_topi[t*2+0] = i1; g_topi[t*2+1] = i2;
        g_topw[t*2+0] = p[i1]; g_topw[t*2+1] = p[i2];
        atomicAdd(&g_cnt[i1], 1); atomicAdd(&g_cnt[i2], 1);
    }
}

__global__ void prefix_kernel(){
    int off = 0, nt = 0;
    for (int e = 0; e < NE; e++){
        g_cur[e] = off;
        int c = g_cnt[e];
        int tiles = (c + 127) >> 7;
        for (int j = 0; j < tiles; j++){
            g_tileE[nt] = e;
            g_tileRow0[nt] = off + j*128;
            g_tileRows[nt] = min(128, c - j*128);
            nt++;
        }
        off += c;
    }
    g_ntiles = nt;
}

__global__ void scatter_kernel(){
    int t = blockIdx.x * blockDim.x + threadIdx.x;
    if (t >= Tn) return;
    #pragma unroll
    for (int s = 0; s < 2; s++){
        int e = g_topi[t*2+s];
        int p = atomicAdd(&g_cur[e], 1);
        g_tok[p] = t;
        g_w[p]   = g_topw[t*2+s];
    }
}

// ================== GEMM1: fp16 mma.sync, CTA 128(M)x64(N) dual-mat, BK=64 halves ==================
// (R13 256-thread configuration — the 128-thread variant regressed in R14)
// stage layout (32KB): A @0 (128x64h=16KB), Bg @16384 (8KB), Bu @24576 (8KB); 3 stages, 2 CTA/SM
#define G1_STAGE 32768
#define SMEM1 (3*G1_STAGE)

__global__ void __launch_bounds__(256, 2) gemm1_kernel(int colOffset)
{
    extern __shared__ char smem[];
    __shared__ int toks[128];
    uint32_t sb = smem_u32(smem);
    int bt = blockIdx.x;                       // row tile (x fastest: weight slices shared in L2)
    if (bt >= g_ntiles) return;
    int e = g_tileE[bt], row0 = g_tileRow0[bt], rows = g_tileRows[bt];
    int colBase = colOffset + blockIdx.y * 64;
    int tid = threadIdx.x, wid = tid >> 5, lane = tid & 31;

    if (tid < 128) toks[tid] = g_tok[row0 + (tid < rows ? tid : 0)];
    __syncthreads();

    const __half* Gb = g_wg_h + ((size_t)e*Id + colBase) * Hd;
    const __half* Ub = g_wu_h + ((size_t)e*Id + colBase) * Hd;

    int ai_r[4], ai_c[4];
    #pragma unroll
    for (int i = 0; i < 4; i++){ int idx = tid + i*256; ai_r[i] = idx >> 3; ai_c[i] = idx & 7; }

    auto load_stage = [&](int sidx, int k0){
        uint32_t base = sb + sidx*G1_STAGE;
        #pragma unroll
        for (int i = 0; i < 4; i++){
            uint32_t off = (uint32_t)(ai_r[i]*128 + ai_c[i]*16);
            cp16u(base + sw128(off), g_hid_h + (size_t)toks[ai_r[i]]*Hd + k0 + ai_c[i]*8);
        }
        #pragma unroll
        for (int i = 4; i < 6; i++){
            int idx = tid + i*256 - 1024; int r = idx >> 3, c = idx & 7;
            uint32_t off = (uint32_t)(r*128 + c*16);
            cp16u(base + 16384 + sw128(off), Gb + (size_t)r*Hd + k0 + c*8);
        }
        #pragma unroll
        for (int i = 6; i < 8; i++){
            int idx = tid + i*256 - 1536; int r = idx >> 3, c = idx & 7;
            uint32_t off = (uint32_t)(r*128 + c*16);
            cp16u(base + 24576 + sw128(off), Ub + (size_t)r*Hd + k0 + c*8);
        }
        CP_COMMIT();
    };

    int wm = wid & 3, wn = wid >> 2;   // 4x2 warps over 128x64
    float cg[2][4][4], cu[2][4][4];
    #pragma unroll
    for (int a = 0; a < 2; a++)
      #pragma unroll
      for (int b = 0; b < 4; b++)
        #pragma unroll
        for (int c = 0; c < 4; c++){ cg[a][b][c] = 0.f; cu[a][b][c] = 0.f; }

    int a_row = (lane & 15);
    int a_hi  = (lane >> 4) * 16;
    int b_row = (lane & 7) + ((lane >> 4) ? 8 : 0);
    int b_hi  = ((lane >> 3) & 1) * 16;

    const int KT = Hd / 64;    // 32
    load_stage(0, 0);
    load_stage(1, 64);

    int sidx = 0;                       // stage of iter k (mod 3)
    for (int k = 0; k < KT; k++){
        if (k + 1 < KT) { CP_WAIT1(); } else { CP_WAIT0(); }
        __syncthreads();
        if (k + 2 < KT){
            int ns = sidx + 2; if (ns >= 3) ns -= 3;
            load_stage(ns, (k+2)*64);
        }
        uint32_t base = sb + sidx*G1_STAGE;
        #pragma unroll
        for (int s = 0; s < 4; s++){
            uint32_t af[2][4];
            #pragma unroll
            for (int mi = 0; mi < 2; mi++){
                int r = wm*32 + mi*16 + a_row;
                ldm_x4(af[mi][0], af[mi][1], af[mi][2], af[mi][3],
                       base + sw128((uint32_t)(r*128 + s*32 + a_hi)));
            }
            #pragma unroll
            for (int nj = 0; nj < 2; nj++){
                int r = wn*32 + nj*16 + b_row;
                uint32_t off = sw128((uint32_t)(r*128 + s*32 + b_hi));
                uint32_t bg0,bg1,bg2,bg3, bu0,bu1,bu2,bu3;
                ldm_x4(bg0,bg1,bg2,bg3, base + 16384 + off);
                ldm_x4(bu0,bu1,bu2,bu3, base + 24576 + off);
                #pragma unroll
                for (int mi = 0; mi < 2; mi++){
                    mma_f16(cg[mi][nj*2+0], af[mi], bg0, bg1);
                    mma_f16(cg[mi][nj*2+1], af[mi], bg2, bg3);
                    mma_f16(cu[mi][nj*2+0], af[mi], bu0, bu1);
                    mma_f16(cu[mi][nj*2+1], af[mi], bu2, bu3);
                }
            }
        }
        sidx++; if (sidx >= 3) sidx = 0;
    }

    // epilogue: h = gelu(g)*u -> fp16
    int grp = lane >> 2, tg = lane & 3;
    #pragma unroll
    for (int mi = 0; mi < 2; mi++)
      #pragma unroll
      for (int nf = 0; nf < 4; nf++){
        int r0 = wm*32 + mi*16 + grp;
        int gc = colBase + wn*32 + nf*8 + tg*2;
        if (r0 < rows){
            size_t o = (size_t)(row0 + r0)*Id + gc;
            *(__half2*)(g_h_h + o) = __floats2half2_rn(
                gelu_exact(cg[mi][nf][0]) * cu[mi][nf][0],
                gelu_exact(cg[mi][nf][1]) * cu[mi][nf][1]);
        }
        if (r0 + 8 < rows){
            size_t o = (size_t)(row0 + r0 + 8)*Id + gc;
            *(__half2*)(g_h_h + o) = __floats2half2_rn(
                gelu_exact(cg[mi][nf][2]) * cu[mi][nf][2],
                gelu_exact(cg[mi][nf][3]) * cu[mi][nf][3]);
        }
      }
}

// ================== GEMM2: fp16 mma.sync, CTA 128x128, 128 threads, warp tile 64x64 ==================
// grid: (Hd/128=16 cols = x fastest, rowtiles = y); kOffset selects the K chunk
// stage layout (32KB): A @0 (16KB), B @16384 (16KB); 3 stages, 2 CTA/SM (128 thr each)
#define G2_STAGE 32768
#define SMEM2 (3*G2_STAGE)
#define G2_KCHUNK 2048

__global__ void __launch_bounds__(128, 2) gemm2_kernel(float* __restrict__ outp, int kOffset)
{
    extern __shared__ char smem[];
    __shared__ int   toks[128];
    __shared__ float ws[128];
    uint32_t sb = smem_u32(smem);
    int bt = blockIdx.y;                       // row tile
    if (bt >= g_ntiles) return;
    int e = g_tileE[bt], row0 = g_tileRow0[bt], rows = g_tileRows[bt];
    int colBase = blockIdx.x * 128;            // column tile (x fastest)
    int tid = threadIdx.x, wid = tid >> 5, lane = tid & 31;

    {
        int r = tid < rows ? tid : 0;
        toks[tid] = g_tok[row0 + r];
        ws[tid]   = g_w[row0 + r];
    }
    __syncthreads();

    const __half* Bb = g_wd_h + ((size_t)e*Hd + colBase) * Id;

    auto load_stage = [&](int sidx, int k0){
        uint32_t base = sb + sidx*G2_STAGE;
        #pragma unroll
        for (int i = 0; i < 8; i++){
            int idx = tid + i*128; int r = idx >> 3, c = idx & 7;
            int ar = row0 + (r < rows ? r : 0);
            uint32_t off = (uint32_t)(r*128 + c*16);
            cp16u(base + sw128(off), g_h_h + (size_t)ar*Id + k0 + c*8);
        }
        #pragma unroll
        for (int i = 0; i < 8; i++){
            int idx = tid + i*128; int r = idx >> 3, c = idx & 7;
            uint32_t off = (uint32_t)(r*128 + c*16);
            cp16u(base + 16384 + sw128(off), Bb + (size_t)r*Id + k0 + c*8);
        }
        CP_COMMIT();
    };

    int wm = wid & 1, wn = wid >> 1;   // 2x2 warps over 128x128 (warp 64x64)
    float cc[4][8][4];
    #pragma unroll
    for (int a = 0; a < 4; a++)
      #pragma unroll
      for (int b = 0; b < 8; b++)
        #pragma unroll
        for (int c = 0; c < 4; c++) cc[a][b][c] = 0.f;

    int a_row = (lane & 15);
    int a_hi  = (lane >> 4) * 16;
    int b_row = (lane & 7) + ((lane >> 4) ? 8 : 0);
    int b_hi  = ((lane >> 3) & 1) * 16;

    const int KT = G2_KCHUNK / 64;    // 32
    load_stage(0, kOffset);
    load_stage(1, kOffset + 64);

    int sidx = 0;
    for (int k = 0; k < KT; k++){
        if (k + 1 < KT) { CP_WAIT1(); } else { CP_WAIT0(); }
        __syncthreads();
        if (k + 2 < KT){
            int ns = sidx + 2; if (ns >= 3) ns -= 3;
            load_stage(ns, kOffset + (k+2)*64);
        }
        uint32_t base = sb + sidx*G2_STAGE;
        #pragma unroll
        for (int s = 0; s < 4; s++){
            uint32_t af[4][4];
            #pragma unroll
            for (int mi = 0; mi < 4; mi++){
                int r = wm*64 + mi*16 + a_row;
                ldm_x4(af[mi][0], af[mi][1], af[mi][2], af[mi][3],
                       base + sw128((uint32_t)(r*128 + s*32 + a_hi)));
            }
            #pragma unroll
            for (int nj = 0; nj < 4; nj++){
                int r = wn*64 + nj*16 + b_row;
                uint32_t b0,b1,b2,b3;
                ldm_x4(b0,b1,b2,b3, base + 16384 + sw128((uint32_t)(r*128 + s*32 + b_hi)));
                #pragma unroll
                for (int mi = 0; mi < 4; mi++){
                    mma_f16(cc[mi][nj*2+0], af[mi], b0, b1);
                    mma_f16(cc[mi][nj*2+1], af[mi], b2, b3);
                }
            }
        }
        sidx++; if (sidx >= 3) sidx = 0;
    }

    // epilogue: out[token] += w * partial (all contributions commute)
    int grp = lane >> 2, tg = lane & 3;
    #pragma unroll
    for (int mi = 0; mi < 4; mi++)
      #pragma unroll
      for (int nf = 0; nf < 8; nf++){
        int r0 = wm*64 + mi*16 + grp;
        int gc = colBase + wn*64 + nf*8 + tg*2;
        if (r0 < rows){
            float w = ws[r0];
            float* o = outp + (size_t)toks[r0]*Hd + gc;
            atomicAdd(o,   w * cc[mi][nf][0]);
            atomicAdd(o+1, w * cc[mi][nf][1]);
        }
        if (r0 + 8 < rows){
            float w = ws[r0+8];
            float* o = outp + (size_t)toks[r0+8]*Hd + gc;
            atomicAdd(o,   w * cc[mi][nf][2]);
            atomicAdd(o+1, w * cc[mi][nf][3]);
        }
      }
}

// ---------------- launch ----------------
extern "C" void kernel_launch(void* const* d_in, const int* in_sizes, int n_in,
                              void* d_out, int out_size)
{
    const float* hidden = (const float*)d_in[0];
    const float* gate_w = (const float*)d_in[1];
    const float* w_gate = (const float*)d_in[2];
    const float* w_up   = (const float*)d_in[3];
    const float* w_down = (const float*)d_in[4];
    float* out = (float*)d_out;

    float* logits_dst;
    if (out_size >= Tn*Hd + Tn*NE) {
        logits_dst = out + (size_t)Tn*Hd;
    } else {
        void* p = nullptr;
        cudaGetSymbolAddress(&p, g_logits_scratch);
        logits_dst = (float*)p;
    }

    void *pwg, *pwu, *pwd;
    cudaGetSymbolAddress(&pwg,  g_wg_h);
    cudaGetSymbolAddress(&pwu,  g_wu_h);
    cudaGetSymbolAddress(&pwd,  g_wd_h);

    // one-time host-side resources (3 side streams — 4 tripped the teardown mem check)
    static cudaStream_t s1 = nullptr, s2 = nullptr, s3 = nullptr;
    static cudaEvent_t evRoot = nullptr, evG2a = nullptr;
    static cudaEvent_t evQ[4]  = {nullptr,nullptr,nullptr,nullptr};
    static cudaEvent_t evWD[4] = {nullptr,nullptr,nullptr,nullptr};
    static cudaEvent_t evG1[4] = {nullptr,nullptr,nullptr,nullptr};
    static bool inited = false;
    if (!inited){
        cudaStreamCreateWithFlags(&s1, cudaStreamNonBlocking);
        cudaStreamCreateWithFlags(&s2, cudaStreamNonBlocking);
        cudaStreamCreateWithFlags(&s3, cudaStreamNonBlocking);
        cudaEventCreateWithFlags(&evRoot, cudaEventDisableTiming);
        cudaEventCreateWithFlags(&evG2a,  cudaEventDisableTiming);
        for (int q = 0; q < 4; q++){
            cudaEventCreateWithFlags(&evQ[q],  cudaEventDisableTiming);
            cudaEventCreateWithFlags(&evWD[q], cudaEventDisableTiming);
            cudaEventCreateWithFlags(&evG1[q], cudaEventDisableTiming);
        }
        cudaFuncSetAttribute(gemm1_kernel, cudaFuncAttributeMaxDynamicSharedMemorySize, SMEM1);
        cudaFuncSetAttribute(gemm2_kernel, cudaFuncAttributeMaxDynamicSharedMemorySize, SMEM2);
        inited = true;
    }

    const int QTR = Id/4;                          // 2048 rows per quarter (per expert)

    // fork: root event on the (capturing) default stream
    zero_kernel<<<1, 32, 0, 0>>>();
    cudaEventRecord(evRoot, 0);
    cudaStreamWaitEvent(s1, evRoot, 0);

    // s1: wg/wu in 4 column-quarters (hidden fp16 produced by the router)
    for (int q = 0; q < 4; q++){
        cvt16_part_kernel<<<2048, 256, 0, s1>>>((const float4*)w_gate, (uint4*)pwg, q*QTR, QTR);
        cvt16_part_kernel<<<2048, 256, 0, s1>>>((const float4*)w_up,   (uint4*)pwu, q*QTR, QTR);
        cudaEventRecord(evQ[q], s1);
    }

    // s2: w_down cvt in K(column)-quarters, AFTER the s1 chain (runs under gemm1)
    cudaStreamWaitEvent(s2, evQ[3], 0);
    for (int q = 0; q < 4; q++){
        cvt16_colpart_kernel<<<2048, 256, 0, s2>>>((const float4*)w_down, (uint4*)pwd,
                                                   NE*Hd, Id/8, q*(G2_KCHUNK/8), G2_KCHUNK/8);
        cudaEventRecord(evWD[q], s2);
    }

    // default stream: routing chain (emits g_hid_h) + output zero
    cudaMemsetAsync(d_out, 0, (size_t)Tn*Hd*sizeof(float), 0);
    router_kernel<<<Tn/8, 256, 0, 0>>>(hidden, gate_w, logits_dst);
    prefix_kernel<<<1, 1, 0, 0>>>();
    scatter_kernel<<<Tn/256, 256, 0, 0>>>();
    cudaEventRecord(evRoot, 0);  // reuse as "routing done" marker for s3's gemm1 quarters
    cudaStreamWaitEvent(s3, evRoot, 0);

    // gemm1 quarters two-lane: q0,q2 on stream0; q1,q3 on s3 (tails/ramps overlap)
    // stream0 q0
    cudaStreamWaitEvent(0, evQ[0], 0);
    gemm1_kernel<<<dim3(72, QTR/64), 256, SMEM1, 0>>>(0*QTR);
    cudaEventRecord(evG1[0], 0);
    // s3 q1
    cudaStreamWaitEvent(s3, evQ[1], 0);
    gemm1_kernel<<<dim3(72, QTR/64), 256, SMEM1, s3>>>(1*QTR);
    cudaEventRecord(evG1[1], s3);
    // stream0 q2
    cudaStreamWaitEvent(0, evQ[2], 0);
    gemm1_kernel<<<dim3(72, QTR/64), 256, SMEM1, 0>>>(2*QTR);
    cudaEventRecord(evG1[2], 0);
    // s3 q3
    cudaStreamWaitEvent(s3, evQ[3], 0);
    gemm1_kernel<<<dim3(72, QTR/64), 256, SMEM1, s3>>>(3*QTR);
    cudaEventRecord(evG1[3], s3);

    // gemm2 K-chunks: c0,c2 on s2 (after the wd cvts on that stream); c1,c3 on stream0
    // s2 c0
    cudaStreamWaitEvent(s2, evG1[0], 0);
    gemm2_kernel<<<dim3(Hd/128, 72), 128, SMEM2, s2>>>(out, 0*G2_KCHUNK);
    // stream0 c1 (stream0's queue: ...q2 -> c1; c1's gates are evG1[1] (s3) + evWD[1])
    cudaStreamWaitEvent(0, evG1[1], 0);
    cudaStreamWaitEvent(0, evWD[1], 0);
    gemm2_kernel<<<dim3(Hd/128, 72), 128, SMEM2, 0>>>(out, 1*G2_KCHUNK);
    // s2 c2
    cudaStreamWaitEvent(s2, evG1[2], 0);
    gemm2_kernel<<<dim3(Hd/128, 72), 128, SMEM2, s2>>>(out, 2*G2_KCHUNK);
    cudaEventRecord(evG2a, s2);
    // stream0 c3
    cudaStreamWaitEvent(0, evG1[3], 0);
    cudaStreamWaitEvent(0, evWD[3], 0);
    gemm2_kernel<<<dim3(Hd/128, 72), 128, SMEM2, 0>>>(out, 3*G2_KCHUNK);

    // join remaining side-stream work back into the capture-origin stream
    cudaStreamWaitEvent(0, evG2a, 0);
}

// round 16
// speedup vs baseline: 1.0214x; 1.0043x over previous
#include <cuda_runtime.h>
#include <cuda_fp16.h>
#include <cstdint>
#include <math.h>

#define Tn 4096
#define Hd 2048
#define Id 8192
#define NE 8
#define NA (2*Tn)
#define MAXT 80

// ---------------- device scratch (no allocs allowed) ----------------
__device__ int    g_cnt[NE];
__device__ int    g_cur[NE];
__device__ int    g_tileE[MAXT], g_tileRow0[MAXT], g_tileRows[MAXT];
__device__ int    g_ntiles;
__device__ int    g_topi[Tn*2];
__device__ float  g_topw[Tn*2];
__device__ int    g_tok[NA];
__device__ float  g_w[NA];
__device__ float  g_logits_scratch[Tn*NE];
__device__ __half g_h_h[(size_t)NA*Id];              // 134 MiB intermediate (fp16)
__device__ __half g_wg_h[(size_t)NE*Id*Hd];          // fp16 weights
__device__ __half g_wu_h[(size_t)NE*Id*Hd];
__device__ __half g_wd_h[(size_t)NE*Hd*Id];
__device__ __half g_hid_h[(size_t)Tn*Hd];

// ---------------- helpers ----------------
__device__ __forceinline__ uint32_t smem_u32(const void* p){
    uint32_t a; asm("{ .reg .u64 t; cvta.to.shared.u64 t, %1; cvt.u32.u64 %0, t; }" : "=r"(a) : "l"(p));
    return a;
}
__device__ __forceinline__ void cp16u(uint32_t sa, const void* g){
    asm volatile("cp.async.cg.shared.global [%0], [%1], 16;\n" :: "r"(sa), "l"(g));
}
#define CP_COMMIT() asm volatile("cp.async.commit_group;\n")
#define CP_WAIT1()  asm volatile("cp.async.wait_group 1;\n")
#define CP_WAIT0()  asm volatile("cp.async.wait_group 0;\n")

__device__ __forceinline__ void ldm_x4(uint32_t& r0, uint32_t& r1, uint32_t& r2, uint32_t& r3, uint32_t addr){
    asm volatile("ldmatrix.sync.aligned.m8n8.x4.shared.b16 {%0,%1,%2,%3}, [%4];\n"
        : "=r"(r0), "=r"(r1), "=r"(r2), "=r"(r3) : "r"(addr));
}
__device__ __forceinline__ void mma_f16(float* c, const uint32_t* a, uint32_t b0, uint32_t b1){
    asm volatile(
      "mma.sync.aligned.m16n8k16.row.col.f32.f16.f16.f32 "
      "{%0,%1,%2,%3}, {%4,%5,%6,%7}, {%8,%9}, {%0,%1,%2,%3};\n"
      : "+f"(c[0]), "+f"(c[1]), "+f"(c[2]), "+f"(c[3])
      : "r"(a[0]), "r"(a[1]), "r"(a[2]), "r"(a[3]), "r"(b0), "r"(b1));
}
__device__ __forceinline__ float gelu_exact(float x){
    return 0.5f * x * (1.0f + erff(x * 0.70710678118654752440f));
}
// swizzle for 128B rows: byte offset within tile
__device__ __forceinline__ uint32_t sw128(uint32_t off){ return off ^ ((off >> 3) & 0x70); }

// ---------------- small kernels ----------------
__global__ void zero_kernel(){ if (threadIdx.x < NE) g_cnt[threadIdx.x] = 0; }

// convert rows [r0, r0+nrows) of each expert of a (NE, Id, Hd) tensor
__global__ void cvt16_part_kernel(const float4* __restrict__ s, uint4* __restrict__ d,
                                  int r0, int nrows){
    const int chunk8 = nrows * (Hd/8);           // uint4s per expert chunk
    const int n8 = NE * chunk8;
    const int base8 = r0 * (Hd/8);
    int i = blockIdx.x * blockDim.x + threadIdx.x;
    int st = gridDim.x * blockDim.x;
    for (; i < n8; i += st){
        int e = i / chunk8, j = i - e * chunk8;
        size_t idx = (size_t)e * (Id*Hd/8) + base8 + j;
        float4 a = s[2*idx], b = s[2*idx+1];
        union { __half2 h[4]; uint4 u; } pk;
        pk.h[0] = __floats2half2_rn(a.x, a.y);
        pk.h[1] = __floats2half2_rn(a.z, a.w);
        pk.h[2] = __floats2half2_rn(b.x, b.y);
        pk.h[3] = __floats2half2_rn(b.z, b.w);
        d[idx] = pk.u;
    }
}

// convert column chunk [c08*8, (c08+nc8)*8) of every row of a (nrows, rowLen8*8) tensor
__global__ void cvt16_colpart_kernel(const float4* __restrict__ s, uint4* __restrict__ d,
                                     int nrows, int rowLen8, int c08, int nc8){
    const int n8 = nrows * nc8;
    int i = blockIdx.x * blockDim.x + threadIdx.x;
    int st = gridDim.x * blockDim.x;
    for (; i < n8; i += st){
        int r = i / nc8, j = i - r * nc8;
        size_t idx = (size_t)r * rowLen8 + c08 + j;
        float4 a = s[2*idx], b = s[2*idx+1];
        union { __half2 h[4]; uint4 u; } pk;
        pk.h[0] = __floats2half2_rn(a.x, a.y);
        pk.h[1] = __floats2half2_rn(a.z, a.w);
        pk.h[2] = __floats2half2_rn(b.x, b.y);
        pk.h[3] = __floats2half2_rn(b.z, b.w);
        d[idx] = pk.u;
    }
}

// router: logits + top2 + also emits fp16 copy of hidden (saves a separate cvt pass)
__global__ void router_kernel(const float* __restrict__ x,
                              const float* __restrict__ gw,
                              float* __restrict__ logits_out)
{
    int warp = threadIdx.x >> 5, lane = threadIdx.x & 31;
    int t = blockIdx.x * 8 + warp;
    if (t >= Tn) return;
    const float* xr = x + (size_t)t * Hd;
    __half* hr = g_hid_h + (size_t)t * Hd;
    float l[NE];
    #pragma unroll
    for (int e = 0; e < NE; e++){
        float acc = 0.f;
        const float* w = gw + e * Hd;
        if (e == 0){
            for (int k = lane; k < Hd; k += 32){
                float v = xr[k];
                acc += v * w[k];
                hr[k] = __float2half_rn(v);
            }
        } else {
            for (int k = lane; k < Hd; k += 32) acc += xr[k] * w[k];
        }
        #pragma unroll
        for (int o = 16; o; o >>= 1) acc += __shfl_xor_sync(0xffffffffu, acc, o);
        l[e] = acc;
    }
    if (lane == 0){
        #pragma unroll
        for (int e = 0; e < NE; e++) logits_out[t*NE + e] = l[e];
        float m = l[0];
        #pragma unroll
        for (int e = 1; e < NE; e++) m = fmaxf(m, l[e]);
        float p[NE]; float s = 0.f;
        #pragma unroll
        for (int e = 0; e < NE; e++){ p[e] = expf(l[e] - m); s += p[e]; }
        float inv = 1.f / s;
        #pragma unroll
        for (int e = 0; e < NE; e++) p[e] *= inv;
        int i1 = 0;
        #pragma unroll
        for (int e = 1; e < NE; e++) if (p[e] > p[i1]) i1 = e;
        int i2 = (i1 == 0) ? 1 : 0;
        #pragma unroll
        for (int e = 0; e < NE; e++){ if (e == i1) continue; if (p[e] > p[i2]) i2 = e; }
        g_topi[t*2+0] = i1; g_topi[t*2+1] = i2;
        g_topw[t*2+0] = p[i1]; g_topw[t*2+1] = p[i2];
        atomicAdd(&g_cnt[i1], 1); atomicAdd(&g_cnt[i2], 1);
    }
}

__global__ void prefix_kernel(){
    int off = 0, nt = 0;
    for (int e = 0; e < NE; e++){
        g_cur[e] = off;
        int c = g_cnt[e];
        int tiles = (c + 127) >> 7;
        for (int j = 0; j < tiles; j++){
            g_tileE[nt] = e;
            g_tileRow0[nt] = off + j*128;
            g_tileRows[nt] = min(128, c - j*128);
            nt++;
        }
        off += c;
    }
    g_ntiles = nt;
}

__global__ void scatter_kernel(){
    int t = blockIdx.x * blockDim.x + threadIdx.x;
    if (t >= Tn) return;
    #pragma unroll
    for (int s = 0; s < 2; s++){
        int e = g_topi[t*2+s];
        int p = atomicAdd(&g_cur[e], 1);
        g_tok[p] = t;
        g_w[p]   = g_topw[t*2+s];
    }
}

// ================== GEMM1: fp16 mma.sync, CTA 128(M)x64(N) dual-mat, BK=64 halves ==================
// (R13 256-thread configuration — best measured)
// stage layout (32KB): A @0 (128x64h=16KB), Bg @16384 (8KB), Bu @24576 (8KB); 3 stages, 2 CTA/SM
#define G1_STAGE 32768
#define SMEM1 (3*G1_STAGE)

__global__ void __launch_bounds__(256, 2) gemm1_kernel(int colOffset)
{
    extern __shared__ char smem[];
    __shared__ int toks[128];
    uint32_t sb = smem_u32(smem);
    int bt = blockIdx.x;                       // row tile (x fastest: weight slices shared in L2)
    if (bt >= g_ntiles) return;
    int e = g_tileE[bt], row0 = g_tileRow0[bt], rows = g_tileRows[bt];
    int colBase = colOffset + blockIdx.y * 64;
    int tid = threadIdx.x, wid = tid >> 5, lane = tid & 31;

    if (tid < 128) toks[tid] = g_tok[row0 + (tid < rows ? tid : 0)];
    __syncthreads();

    const __half* Gb = g_wg_h + ((size_t)e*Id + colBase) * Hd;
    const __half* Ub = g_wu_h + ((size_t)e*Id + colBase) * Hd;

    int ai_r[4], ai_c[4];
    #pragma unroll
    for (int i = 0; i < 4; i++){ int idx = tid + i*256; ai_r[i] = idx >> 3; ai_c[i] = idx & 7; }

    auto load_stage = [&](int sidx, int k0){
        uint32_t base = sb + sidx*G1_STAGE;
        #pragma unroll
        for (int i = 0; i < 4; i++){
            uint32_t off = (uint32_t)(ai_r[i]*128 + ai_c[i]*16);
            cp16u(base + sw128(off), g_hid_h + (size_t)toks[ai_r[i]]*Hd + k0 + ai_c[i]*8);
        }
        #pragma unroll
        for (int i = 4; i < 6; i++){
            int idx = tid + i*256 - 1024; int r = idx >> 3, c = idx & 7;
            uint32_t off = (uint32_t)(r*128 + c*16);
            cp16u(base + 16384 + sw128(off), Gb + (size_t)r*Hd + k0 + c*8);
        }
        #pragma unroll
        for (int i = 6; i < 8; i++){
            int idx = tid + i*256 - 1536; int r = idx >> 3, c = idx & 7;
            uint32_t off = (uint32_t)(r*128 + c*16);
            cp16u(base + 24576 + sw128(off), Ub + (size_t)r*Hd + k0 + c*8);
        }
        CP_COMMIT();
    };

    int wm = wid & 3, wn = wid >> 2;   // 4x2 warps over 128x64
    float cg[2][4][4], cu[2][4][4];
    #pragma unroll
    for (int a = 0; a < 2; a++)
      #pragma unroll
      for (int b = 0; b < 4; b++)
        #pragma unroll
        for (int c = 0; c < 4; c++){ cg[a][b][c] = 0.f; cu[a][b][c] = 0.f; }

    int a_row = (lane & 15);
    int a_hi  = (lane >> 4) * 16;
    int b_row = (lane & 7) + ((lane >> 4) ? 8 : 0);
    int b_hi  = ((lane >> 3) & 1) * 16;

    const int KT = Hd / 64;    // 32
    load_stage(0, 0);
    load_stage(1, 64);

    int sidx = 0;                       // stage of iter k (mod 3)
    for (int k = 0; k < KT; k++){
        if (k + 1 < KT) { CP_WAIT1(); } else { CP_WAIT0(); }
        __syncthreads();
        if (k + 2 < KT){
            int ns = sidx + 2; if (ns >= 3) ns -= 3;
            load_stage(ns, (k+2)*64);
        }
        uint32_t base = sb + sidx*G1_STAGE;
        #pragma unroll
        for (int s = 0; s < 4; s++){
            uint32_t af[2][4];
            #pragma unroll
            for (int mi = 0; mi < 2; mi++){
                int r = wm*32 + mi*16 + a_row;
                ldm_x4(af[mi][0], af[mi][1], af[mi][2], af[mi][3],
                       base + sw128((uint32_t)(r*128 + s*32 + a_hi)));
            }
            #pragma unroll
            for (int nj = 0; nj < 2; nj++){
                int r = wn*32 + nj*16 + b_row;
                uint32_t off = sw128((uint32_t)(r*128 + s*32 + b_hi));
                uint32_t bg0,bg1,bg2,bg3, bu0,bu1,bu2,bu3;
                ldm_x4(bg0,bg1,bg2,bg3, base + 16384 + off);
                ldm_x4(bu0,bu1,bu2,bu3, base + 24576 + off);
                #pragma unroll
                for (int mi = 0; mi < 2; mi++){
                    mma_f16(cg[mi][nj*2+0], af[mi], bg0, bg1);
                    mma_f16(cg[mi][nj*2+1], af[mi], bg2, bg3);
                    mma_f16(cu[mi][nj*2+0], af[mi], bu0, bu1);
                    mma_f16(cu[mi][nj*2+1], af[mi], bu2, bu3);
                }
            }
        }
        sidx++; if (sidx >= 3) sidx = 0;
    }

    // epilogue: h = gelu(g)*u -> fp16
    int grp = lane >> 2, tg = lane & 3;
    #pragma unroll
    for (int mi = 0; mi < 2; mi++)
      #pragma unroll
      for (int nf = 0; nf < 4; nf++){
        int r0 = wm*32 + mi*16 + grp;
        int gc = colBase + wn*32 + nf*8 + tg*2;
        if (r0 < rows){
            size_t o = (size_t)(row0 + r0)*Id + gc;
            *(__half2*)(g_h_h + o) = __floats2half2_rn(
                gelu_exact(cg[mi][nf][0]) * cu[mi][nf][0],
                gelu_exact(cg[mi][nf][1]) * cu[mi][nf][1]);
        }
        if (r0 + 8 < rows){
            size_t o = (size_t)(row0 + r0 + 8)*Id + gc;
            *(__half2*)(g_h_h + o) = __floats2half2_rn(
                gelu_exact(cg[mi][nf][2]) * cu[mi][nf][2],
                gelu_exact(cg[mi][nf][3]) * cu[mi][nf][3]);
        }
      }
}

// ================== GEMM2: fp16 mma.sync, CTA 128x128, 128 threads, warp tile 64x64 ==================
// grid: (Hd/128=16 cols = x fastest, rowtiles = y); kOffset/kLen select the K chunk
// stage layout (32KB): A @0 (16KB), B @16384 (16KB); 3 stages, 2 CTA/SM (128 thr each)
#define G2_STAGE 32768
#define SMEM2 (3*G2_STAGE)
#define G2_KCHUNK 4096

__global__ void __launch_bounds__(128, 2) gemm2_kernel(float* __restrict__ outp, int kOffset)
{
    extern __shared__ char smem[];
    __shared__ int   toks[128];
    __shared__ float ws[128];
    uint32_t sb = smem_u32(smem);
    int bt = blockIdx.y;                       // row tile
    if (bt >= g_ntiles) return;
    int e = g_tileE[bt], row0 = g_tileRow0[bt], rows = g_tileRows[bt];
    int colBase = blockIdx.x * 128;            // column tile (x fastest)
    int tid = threadIdx.x, wid = tid >> 5, lane = tid & 31;

    {
        int r = tid < rows ? tid : 0;
        toks[tid] = g_tok[row0 + r];
        ws[tid]   = g_w[row0 + r];
    }
    __syncthreads();

    const __half* Bb = g_wd_h + ((size_t)e*Hd + colBase) * Id;

    auto load_stage = [&](int sidx, int k0){
        uint32_t base = sb + sidx*G2_STAGE;
        #pragma unroll
        for (int i = 0; i < 8; i++){
            int idx = tid + i*128; int r = idx >> 3, c = idx & 7;
            int ar = row0 + (r < rows ? r : 0);
            uint32_t off = (uint32_t)(r*128 + c*16);
            cp16u(base + sw128(off), g_h_h + (size_t)ar*Id + k0 + c*8);
        }
        #pragma unroll
        for (int i = 0; i < 8; i++){
            int idx = tid + i*128; int r = idx >> 3, c = idx & 7;
            uint32_t off = (uint32_t)(r*128 + c*16);
            cp16u(base + 16384 + sw128(off), Bb + (size_t)r*Id + k0 + c*8);
        }
        CP_COMMIT();
    };

    int wm = wid & 1, wn = wid >> 1;   // 2x2 warps over 128x128 (warp 64x64)
    float cc[4][8][4];
    #pragma unroll
    for (int a = 0; a < 4; a++)
      #pragma unroll
      for (int b = 0; b < 8; b++)
        #pragma unroll
        for (int c = 0; c < 4; c++) cc[a][b][c] = 0.f;

    int a_row = (lane & 15);
    int a_hi  = (lane >> 4) * 16;
    int b_row = (lane & 7) + ((lane >> 4) ? 8 : 0);
    int b_hi  = ((lane >> 3) & 1) * 16;

    const int KT = G2_KCHUNK / 64;    // 64
    load_stage(0, kOffset);
    load_stage(1, kOffset + 64);

    int sidx = 0;
    for (int k = 0; k < KT; k++){
        if (k + 1 < KT) { CP_WAIT1(); } else { CP_WAIT0(); }
        __syncthreads();
        if (k + 2 < KT){
            int ns = sidx + 2; if (ns >= 3) ns -= 3;
            load_stage(ns, kOffset + (k+2)*64);
        }
        uint32_t base = sb + sidx*G2_STAGE;
        #pragma unroll
        for (int s = 0; s < 4; s++){
            uint32_t af[4][4];
            #pragma unroll
            for (int mi = 0; mi < 4; mi++){
                int r = wm*64 + mi*16 + a_row;
                ldm_x4(af[mi][0], af[mi][1], af[mi][2], af[mi][3],
                       base + sw128((uint32_t)(r*128 + s*32 + a_hi)));
            }
            #pragma unroll
            for (int nj = 0; nj < 4; nj++){
                int r = wn*64 + nj*16 + b_row;
                uint32_t b0,b1,b2,b3;
                ldm_x4(b0,b1,b2,b3, base + 16384 + sw128((uint32_t)(r*128 + s*32 + b_hi)));
                #pragma unroll
                for (int mi = 0; mi < 4; mi++){
                    mma_f16(cc[mi][nj*2+0], af[mi], b0, b1);
                    mma_f16(cc[mi][nj*2+1], af[mi], b2, b3);
                }
            }
        }
        sidx++; if (sidx >= 3) sidx = 0;
    }

    // epilogue: out[token] += w * partial (all contributions commute)
    int grp = lane >> 2, tg = lane & 3;
    #pragma unroll
    for (int mi = 0; mi < 4; mi++)
      #pragma unroll
      for (int nf = 0; nf < 8; nf++){
        int r0 = wm*64 + mi*16 + grp;
        int gc = colBase + wn*64 + nf*8 + tg*2;
        if (r0 < rows){
            float w = ws[r0];
            float* o = outp + (size_t)toks[r0]*Hd + gc;
            atomicAdd(o,   w * cc[mi][nf][0]);
            atomicAdd(o+1, w * cc[mi][nf][1]);
        }
        if (r0 + 8 < rows){
            float w = ws[r0+8];
            float* o = outp + (size_t)toks[r0+8]*Hd + gc;
            atomicAdd(o,   w * cc[mi][nf][2]);
            atomicAdd(o+1, w * cc[mi][nf][3]);
        }
      }
}

// ---------------- launch ----------------
extern "C" void kernel_launch(void* const* d_in, const int* in_sizes, int n_in,
                              void* d_out, int out_size)
{
    const float* hidden = (const float*)d_in[0];
    const float* gate_w = (const float*)d_in[1];
    const float* w_gate = (const float*)d_in[2];
    const float* w_up   = (const float*)d_in[3];
    const float* w_down = (const float*)d_in[4];
    float* out = (float*)d_out;

    float* logits_dst;
    if (out_size >= Tn*Hd + Tn*NE) {
        logits_dst = out + (size_t)Tn*Hd;
    } else {
        void* p = nullptr;
        cudaGetSymbolAddress(&p, g_logits_scratch);
        logits_dst = (float*)p;
    }

    void *pwg, *pwu, *pwd;
    cudaGetSymbolAddress(&pwg,  g_wg_h);
    cudaGetSymbolAddress(&pwu,  g_wu_h);
    cudaGetSymbolAddress(&pwd,  g_wd_h);

    // one-time host-side resources (3 side streams — 4 tripped the teardown mem check)
    static cudaStream_t s1 = nullptr, s2 = nullptr, s3 = nullptr;
    static cudaEvent_t evRoot = nullptr, evG2a = nullptr, evG2b = nullptr;
    static cudaEvent_t evQ[4]  = {nullptr,nullptr,nullptr,nullptr};
    static cudaEvent_t evWD[4] = {nullptr,nullptr,nullptr,nullptr};
    static cudaEvent_t evG1[4] = {nullptr,nullptr,nullptr,nullptr};
    static bool inited = false;
    if (!inited){
        cudaStreamCreateWithFlags(&s1, cudaStreamNonBlocking);
        cudaStreamCreateWithFlags(&s2, cudaStreamNonBlocking);
        cudaStreamCreateWithFlags(&s3, cudaStreamNonBlocking);
        cudaEventCreateWithFlags(&evRoot, cudaEventDisableTiming);
        cudaEventCreateWithFlags(&evG2a,  cudaEventDisableTiming);
        cudaEventCreateWithFlags(&evG2b,  cudaEventDisableTiming);
        for (int q = 0; q < 4; q++){
            cudaEventCreateWithFlags(&evQ[q],  cudaEventDisableTiming);
            cudaEventCreateWithFlags(&evWD[q], cudaEventDisableTiming);
            cudaEventCreateWithFlags(&evG1[q], cudaEventDisableTiming);
        }
        cudaFuncSetAttribute(gemm1_kernel, cudaFuncAttributeMaxDynamicSharedMemorySize, SMEM1);
        cudaFuncSetAttribute(gemm2_kernel, cudaFuncAttributeMaxDynamicSharedMemorySize, SMEM2);
        inited = true;
    }

    const int QTR = Id/4;                          // 2048 rows per quarter (per expert)

    // fork: root event on the (capturing) default stream
    zero_kernel<<<1, 32, 0, 0>>>();
    cudaEventRecord(evRoot, 0);
    cudaStreamWaitEvent(s1, evRoot, 0);

    // s1: wg/wu in 4 column-quarters (hidden fp16 produced by the router)
    for (int q = 0; q < 4; q++){
        cvt16_part_kernel<<<2048, 256, 0, s1>>>((const float4*)w_gate, (uint4*)pwg, q*QTR, QTR);
        cvt16_part_kernel<<<2048, 256, 0, s1>>>((const float4*)w_up,   (uint4*)pwu, q*QTR, QTR);
        cudaEventRecord(evQ[q], s1);
    }

    // s2: w_down cvt in K(column)-quarters, AFTER the s1 chain (runs under gemm1)
    cudaStreamWaitEvent(s2, evQ[3], 0);
    for (int q = 0; q < 4; q++){
        cvt16_colpart_kernel<<<2048, 256, 0, s2>>>((const float4*)w_down, (uint4*)pwd,
                                                   NE*Hd, Id/8, q*(Id/4/8), Id/4/8);
        cudaEventRecord(evWD[q], s2);
    }

    // default stream: routing chain (emits g_hid_h) + output zero
    cudaMemsetAsync(d_out, 0, (size_t)Tn*Hd*sizeof(float), 0);
    router_kernel<<<Tn/8, 256, 0, 0>>>(hidden, gate_w, logits_dst);
    prefix_kernel<<<1, 1, 0, 0>>>();
    scatter_kernel<<<Tn/256, 256, 0, 0>>>();

    // gemm1 in 4 column-quarter chunks, each gated on its cvt pair (serial on stream0)
    for (int q = 0; q < 4; q++){
        cudaStreamWaitEvent(0, evQ[q], 0);
        gemm1_kernel<<<dim3(72, QTR/64), 256, SMEM1, 0>>>(q*QTR);
        cudaEventRecord(evG1[q], 0);
    }

    // gemm2 in 2 K-chunks of 4096 (halves the atomic epilogue rounds):
    // chunk0 on s3 gated on gemm1 half (q0,q1) + wd half; chunk1 on s2 gated on the rest
    cudaStreamWaitEvent(s3, evG1[1], 0);
    cudaStreamWaitEvent(s3, evWD[1], 0);
    gemm2_kernel<<<dim3(Hd/128, 72), 128, SMEM2, s3>>>(out, 0*G2_KCHUNK);
    cudaEventRecord(evG2a, s3);

    cudaStreamWaitEvent(s2, evG1[3], 0);
    gemm2_kernel<<<dim3(Hd/128, 72), 128, SMEM2, s2>>>(out, 1*G2_KCHUNK);
    cudaEventRecord(evG2b, s2);

    // join everything back into the capture-origin stream
    cudaStreamWaitEvent(0, evG2a, 0);
    cudaStreamWaitEvent(0, evG2b, 0);
}

// round 17
// speedup vs baseline: 1.0225x; 1.0011x over previous
#include <cuda_runtime.h>
#include <cuda_fp16.h>
#include <cstdint>
#include <math.h>

#define Tn 4096
#define Hd 2048
#define Id 8192
#define NE 8
#define NA (2*Tn)
#define MAXT 80

// ---------------- device scratch (no allocs allowed) ----------------
__device__ int    g_cnt[NE];
__device__ int    g_cur[NE];
__device__ int    g_tileE[MAXT], g_tileRow0[MAXT], g_tileRows[MAXT];
__device__ int    g_ntiles;
__device__ int    g_topi[Tn*2];
__device__ float  g_topw[Tn*2];
__device__ int    g_tok[NA];
__device__ float  g_w[NA];
__device__ float  g_logits_scratch[Tn*NE];
__device__ __half g_h_h[(size_t)NA*Id];              // 134 MiB intermediate (fp16)
__device__ __half g_wg_h[(size_t)NE*Id*Hd];          // fp16 weights
__device__ __half g_wu_h[(size_t)NE*Id*Hd];
__device__ __half g_wd_h[(size_t)NE*Hd*Id];
__device__ __half g_hid_h[(size_t)Tn*Hd];

// ---------------- helpers ----------------
__device__ __forceinline__ uint32_t smem_u32(const void* p){
    uint32_t a; asm("{ .reg .u64 t; cvta.to.shared.u64 t, %1; cvt.u32.u64 %0, t; }" : "=r"(a) : "l"(p));
    return a;
}
__device__ __forceinline__ void cp16u(uint32_t sa, const void* g){
    asm volatile("cp.async.cg.shared.global [%0], [%1], 16;\n" :: "r"(sa), "l"(g));
}
#define CP_COMMIT() asm volatile("cp.async.commit_group;\n")
#define CP_WAIT1()  asm volatile("cp.async.wait_group 1;\n")
#define CP_WAIT0()  asm volatile("cp.async.wait_group 0;\n")

__device__ __forceinline__ void ldm_x4(uint32_t& r0, uint32_t& r1, uint32_t& r2, uint32_t& r3, uint32_t addr){
    asm volatile("ldmatrix.sync.aligned.m8n8.x4.shared.b16 {%0,%1,%2,%3}, [%4];\n"
        : "=r"(r0), "=r"(r1), "=r"(r2), "=r"(r3) : "r"(addr));
}
__device__ __forceinline__ void mma_f16(float* c, const uint32_t* a, uint32_t b0, uint32_t b1){
    asm volatile(
      "mma.sync.aligned.m16n8k16.row.col.f32.f16.f16.f32 "
      "{%0,%1,%2,%3}, {%4,%5,%6,%7}, {%8,%9}, {%0,%1,%2,%3};\n"
      : "+f"(c[0]), "+f"(c[1]), "+f"(c[2]), "+f"(c[3])
      : "r"(a[0]), "r"(a[1]), "r"(a[2]), "r"(a[3]), "r"(b0), "r"(b1));
}
__device__ __forceinline__ float gelu_exact(float x){
    return 0.5f * x * (1.0f + erff(x * 0.70710678118654752440f));
}
// swizzle for 128B rows: byte offset within tile
__device__ __forceinline__ uint32_t sw128(uint32_t off){ return off ^ ((off >> 3) & 0x70); }

// ---------------- small kernels ----------------
__global__ void zero_kernel(){ if (threadIdx.x < NE) g_cnt[threadIdx.x] = 0; }

// convert rows [r0, r0+nrows) of each expert of a (NE, Id, Hd) tensor
__global__ void cvt16_part_kernel(const float4* __restrict__ s, uint4* __restrict__ d,
                                  int r0, int nrows){
    const int chunk8 = nrows * (Hd/8);           // uint4s per expert chunk
    const int n8 = NE * chunk8;
    const int base8 = r0 * (Hd/8);
    int i = blockIdx.x * blockDim.x + threadIdx.x;
    int st = gridDim.x * blockDim.x;
    for (; i < n8; i += st){
        int e = i / chunk8, j = i - e * chunk8;
        size_t idx = (size_t)e * (Id*Hd/8) + base8 + j;
        float4 a = s[2*idx], b = s[2*idx+1];
        union { __half2 h[4]; uint4 u; } pk;
        pk.h[0] = __floats2half2_rn(a.x, a.y);
        pk.h[1] = __floats2half2_rn(a.z, a.w);
        pk.h[2] = __floats2half2_rn(b.x, b.y);
        pk.h[3] = __floats2half2_rn(b.z, b.w);
        d[idx] = pk.u;
    }
}

// convert column chunk [c08*8, (c08+nc8)*8) of every row of a (nrows, rowLen8*8) tensor
__global__ void cvt16_colpart_kernel(const float4* __restrict__ s, uint4* __restrict__ d,
                                     int nrows, int rowLen8, int c08, int nc8){
    const int n8 = nrows * nc8;
    int i = blockIdx.x * blockDim.x + threadIdx.x;
    int st = gridDim.x * blockDim.x;
    for (; i < n8; i += st){
        int r = i / nc8, j = i - r * nc8;
        size_t idx = (size_t)r * rowLen8 + c08 + j;
        float4 a = s[2*idx], b = s[2*idx+1];
        union { __half2 h[4]; uint4 u; } pk;
        pk.h[0] = __floats2half2_rn(a.x, a.y);
        pk.h[1] = __floats2half2_rn(a.z, a.w);
        pk.h[2] = __floats2half2_rn(b.x, b.y);
        pk.h[3] = __floats2half2_rn(b.z, b.w);
        d[idx] = pk.u;
    }
}

// router: logits + top2 + also emits fp16 copy of hidden (saves a separate cvt pass)
__global__ void router_kernel(const float* __restrict__ x,
                              const float* __restrict__ gw,
                              float* __restrict__ logits_out)
{
    int warp = threadIdx.x >> 5, lane = threadIdx.x & 31;
    int t = blockIdx.x * 8 + warp;
    if (t >= Tn) return;
    const float* xr = x + (size_t)t * Hd;
    __half* hr = g_hid_h + (size_t)t * Hd;
    float l[NE];
    #pragma unroll
    for (int e = 0; e < NE; e++){
        float acc = 0.f;
        const float* w = gw + e * Hd;
        if (e == 0){
            for (int k = lane; k < Hd; k += 32){
                float v = xr[k];
                acc += v * w[k];
                hr[k] = __float2half_rn(v);
            }
        } else {
            for (int k = lane; k < Hd; k += 32) acc += xr[k] * w[k];
        }
        #pragma unroll
        for (int o = 16; o; o >>= 1) acc += __shfl_xor_sync(0xffffffffu, acc, o);
        l[e] = acc;
    }
    if (lane == 0){
        #pragma unroll
        for (int e = 0; e < NE; e++) logits_out[t*NE + e] = l[e];
        float m = l[0];
        #pragma unroll
        for (int e = 1; e < NE; e++) m = fmaxf(m, l[e]);
        float p[NE]; float s = 0.f;
        #pragma unroll
        for (int e = 0; e < NE; e++){ p[e] = expf(l[e] - m); s += p[e]; }
        float inv = 1.f / s;
        #pragma unroll
        for (int e = 0; e < NE; e++) p[e] *= inv;
        int i1 = 0;
        #pragma unroll
        for (int e = 1; e < NE; e++) if (p[e] > p[i1]) i1 = e;
        int i2 = (i1 == 0) ? 1 : 0;
        #pragma unroll
        for (int e = 0; e < NE; e++){ if (e == i1) continue; if (p[e] > p[i2]) i2 = e; }
        g_topi[t*2+0] = i1; g_topi[t*2+1] = i2;
        g_topw[t*2+0] = p[i1]; g_topw[t*2+1] = p[i2];
        atomicAdd(&g_cnt[i1], 1); atomicAdd(&g_cnt[i2], 1);
    }
}

__global__ void prefix_kernel(){
    int off = 0, nt = 0;
    for (int e = 0; e < NE; e++){
        g_cur[e] = off;
        int c = g_cnt[e];
        int tiles = (c + 127) >> 7;
        for (int j = 0; j < tiles; j++){
            g_tileE[nt] = e;
            g_tileRow0[nt] = off + j*128;
            g_tileRows[nt] = min(128, c - j*128);
            nt++;
        }
        off += c;
    }
    g_ntiles = nt;
}

__global__ void scatter_kernel(){
    int t = blockIdx.x * blockDim.x + threadIdx.x;
    if (t >= Tn) return;
    #pragma unroll
    for (int s = 0; s < 2; s++){
        int e = g_topi[t*2+s];
        int p = atomicAdd(&g_cur[e], 1);
        g_tok[p] = t;
        g_w[p]   = g_topw[t*2+s];
    }
}

// ================== GEMM1: fp16 mma.sync, CTA 128(M)x64(N) dual-mat, BK=64 halves ==================
// (R13 256-thread configuration — best measured)
// stage layout (32KB): A @0 (128x64h=16KB), Bg @16384 (8KB), Bu @24576 (8KB); 3 stages, 2 CTA/SM
#define G1_STAGE 32768
#define SMEM1 (3*G1_STAGE)

__global__ void __launch_bounds__(256, 2) gemm1_kernel(int colOffset)
{
    extern __shared__ char smem[];
    __shared__ int toks[128];
    uint32_t sb = smem_u32(smem);
    int bt = blockIdx.x;                       // row tile (x fastest: weight slices shared in L2)
    if (bt >= g_ntiles) return;
    int e = g_tileE[bt], row0 = g_tileRow0[bt], rows = g_tileRows[bt];
    int colBase = colOffset + blockIdx.y * 64;
    int tid = threadIdx.x, wid = tid >> 5, lane = tid & 31;

    if (tid < 128) toks[tid] = g_tok[row0 + (tid < rows ? tid : 0)];
    __syncthreads();

    const __half* Gb = g_wg_h + ((size_t)e*Id + colBase) * Hd;
    const __half* Ub = g_wu_h + ((size_t)e*Id + colBase) * Hd;

    int ai_r[4], ai_c[4];
    #pragma unroll
    for (int i = 0; i < 4; i++){ int idx = tid + i*256; ai_r[i] = idx >> 3; ai_c[i] = idx & 7; }

    auto load_stage = [&](int sidx, int k0){
        uint32_t base = sb + sidx*G1_STAGE;
        #pragma unroll
        for (int i = 0; i < 4; i++){
            uint32_t off = (uint32_t)(ai_r[i]*128 + ai_c[i]*16);
            cp16u(base + sw128(off), g_hid_h + (size_t)toks[ai_r[i]]*Hd + k0 + ai_c[i]*8);
        }
        #pragma unroll
        for (int i = 4; i < 6; i++){
            int idx = tid + i*256 - 1024; int r = idx >> 3, c = idx & 7;
            uint32_t off = (uint32_t)(r*128 + c*16);
            cp16u(base + 16384 + sw128(off), Gb + (size_t)r*Hd + k0 + c*8);
        }
        #pragma unroll
        for (int i = 6; i < 8; i++){
            int idx = tid + i*256 - 1536; int r = idx >> 3, c = idx & 7;
            uint32_t off = (uint32_t)(r*128 + c*16);
            cp16u(base + 24576 + sw128(off), Ub + (size_t)r*Hd + k0 + c*8);
        }
        CP_COMMIT();
    };

    int wm = wid & 3, wn = wid >> 2;   // 4x2 warps over 128x64
    float cg[2][4][4], cu[2][4][4];
    #pragma unroll
    for (int a = 0; a < 2; a++)
      #pragma unroll
      for (int b = 0; b < 4; b++)
        #pragma unroll
        for (int c = 0; c < 4; c++){ cg[a][b][c] = 0.f; cu[a][b][c] = 0.f; }

    int a_row = (lane & 15);
    int a_hi  = (lane >> 4) * 16;
    int b_row = (lane & 7) + ((lane >> 4) ? 8 : 0);
    int b_hi  = ((lane >> 3) & 1) * 16;

    const int KT = Hd / 64;    // 32
    load_stage(0, 0);
    load_stage(1, 64);

    int sidx = 0;                       // stage of iter k (mod 3)
    for (int k = 0; k < KT; k++){
        if (k + 1 < KT) { CP_WAIT1(); } else { CP_WAIT0(); }
        __syncthreads();
        if (k + 2 < KT){
            int ns = sidx + 2; if (ns >= 3) ns -= 3;
            load_stage(ns, (k+2)*64);
        }
        uint32_t base = sb + sidx*G1_STAGE;
        #pragma unroll
        for (int s = 0; s < 4; s++){
            uint32_t af[2][4];
            #pragma unroll
            for (int mi = 0; mi < 2; mi++){
                int r = wm*32 + mi*16 + a_row;
                ldm_x4(af[mi][0], af[mi][1], af[mi][2], af[mi][3],
                       base + sw128((uint32_t)(r*128 + s*32 + a_hi)));
            }
            #pragma unroll
            for (int nj = 0; nj < 2; nj++){
                int r = wn*32 + nj*16 + b_row;
                uint32_t off = sw128((uint32_t)(r*128 + s*32 + b_hi));
                uint32_t bg0,bg1,bg2,bg3, bu0,bu1,bu2,bu3;
                ldm_x4(bg0,bg1,bg2,bg3, base + 16384 + off);
                ldm_x4(bu0,bu1,bu2,bu3, base + 24576 + off);
                #pragma unroll
                for (int mi = 0; mi < 2; mi++){
                    mma_f16(cg[mi][nj*2+0], af[mi], bg0, bg1);
                    mma_f16(cg[mi][nj*2+1], af[mi], bg2, bg3);
                    mma_f16(cu[mi][nj*2+0], af[mi], bu0, bu1);
                    mma_f16(cu[mi][nj*2+1], af[mi], bu2, bu3);
                }
            }
        }
        sidx++; if (sidx >= 3) sidx = 0;
    }

    // epilogue: h = gelu(g)*u -> fp16
    int grp = lane >> 2, tg = lane & 3;
    #pragma unroll
    for (int mi = 0; mi < 2; mi++)
      #pragma unroll
      for (int nf = 0; nf < 4; nf++){
        int r0 = wm*32 + mi*16 + grp;
        int gc = colBase + wn*32 + nf*8 + tg*2;
        if (r0 < rows){
            size_t o = (size_t)(row0 + r0)*Id + gc;
            *(__half2*)(g_h_h + o) = __floats2half2_rn(
                gelu_exact(cg[mi][nf][0]) * cu[mi][nf][0],
                gelu_exact(cg[mi][nf][1]) * cu[mi][nf][1]);
        }
        if (r0 + 8 < rows){
            size_t o = (size_t)(row0 + r0 + 8)*Id + gc;
            *(__half2*)(g_h_h + o) = __floats2half2_rn(
                gelu_exact(cg[mi][nf][2]) * cu[mi][nf][2],
                gelu_exact(cg[mi][nf][3]) * cu[mi][nf][3]);
        }
      }
}

// ================== GEMM2: fp16 mma.sync, CTA 128x128, 128 threads, warp tile 64x64 ==================
// grid: (Hd/128=16 cols = x fastest, rowtiles = y); kOffset/kLen select the K chunk
// stage layout (32KB): A @0 (16KB), B @16384 (16KB); 3 stages, 2 CTA/SM (128 thr each)
#define G2_STAGE 32768
#define SMEM2 (3*G2_STAGE)
#define G2_KCHUNK 4096

__global__ void __launch_bounds__(128, 2) gemm2_kernel(float* __restrict__ outp, int kOffset)
{
    extern __shared__ char smem[];
    __shared__ int   toks[128];
    __shared__ float ws[128];
    uint32_t sb = smem_u32(smem);
    int bt = blockIdx.y;                       // row tile
    if (bt >= g_ntiles) return;
    int e = g_tileE[bt], row0 = g_tileRow0[bt], rows = g_tileRows[bt];
    int colBase = blockIdx.x * 128;            // column tile (x fastest)
    int tid = threadIdx.x, wid = tid >> 5, lane = tid & 31;

    {
        int r = tid < rows ? tid : 0;
        toks[tid] = g_tok[row0 + r];
        ws[tid]   = g_w[row0 + r];
    }
    __syncthreads();

    const __half* Bb = g_wd_h + ((size_t)e*Hd + colBase) * Id;

    auto load_stage = [&](int sidx, int k0){
        uint32_t base = sb + sidx*G2_STAGE;
        #pragma unroll
        for (int i = 0; i < 8; i++){
            int idx = tid + i*128; int r = idx >> 3, c = idx & 7;
            int ar = row0 + (r < rows ? r : 0);
            uint32_t off = (uint32_t)(r*128 + c*16);
            cp16u(base + sw128(off), g_h_h + (size_t)ar*Id + k0 + c*8);
        }
        #pragma unroll
        for (int i = 0; i < 8; i++){
            int idx = tid + i*128; int r = idx >> 3, c = idx & 7;
            uint32_t off = (uint32_t)(r*128 + c*16);
            cp16u(base + 16384 + sw128(off), Bb + (size_t)r*Id + k0 + c*8);
        }
        CP_COMMIT();
    };

    int wm = wid & 1, wn = wid >> 1;   // 2x2 warps over 128x128 (warp 64x64)
    float cc[4][8][4];
    #pragma unroll
    for (int a = 0; a < 4; a++)
      #pragma unroll
      for (int b = 0; b < 8; b++)
        #pragma unroll
        for (int c = 0; c < 4; c++) cc[a][b][c] = 0.f;

    int a_row = (lane & 15);
    int a_hi  = (lane >> 4) * 16;
    int b_row = (lane & 7) + ((lane >> 4) ? 8 : 0);
    int b_hi  = ((lane >> 3) & 1) * 16;

    const int KT = G2_KCHUNK / 64;    // 64
    load_stage(0, kOffset);
    load_stage(1, kOffset + 64);

    int sidx = 0;
    for (int k = 0; k < KT; k++){
        if (k + 1 < KT) { CP_WAIT1(); } else { CP_WAIT0(); }
        __syncthreads();
        if (k + 2 < KT){
            int ns = sidx + 2; if (ns >= 3) ns -= 3;
            load_stage(ns, kOffset + (k+2)*64);
        }
        uint32_t base = sb + sidx*G2_STAGE;
        #pragma unroll
        for (int s = 0; s < 4; s++){
            uint32_t af[4][4];
            #pragma unroll
            for (int mi = 0; mi < 4; mi++){
                int r = wm*64 + mi*16 + a_row;
                ldm_x4(af[mi][0], af[mi][1], af[mi][2], af[mi][3],
                       base + sw128((uint32_t)(r*128 + s*32 + a_hi)));
            }
            #pragma unroll
            for (int nj = 0; nj < 4; nj++){
                int r = wn*64 + nj*16 + b_row;
                uint32_t b0,b1,b2,b3;
                ldm_x4(b0,b1,b2,b3, base + 16384 + sw128((uint32_t)(r*128 + s*32 + b_hi)));
                #pragma unroll
                for (int mi = 0; mi < 4; mi++){
                    mma_f16(cc[mi][nj*2+0], af[mi], b0, b1);
                    mma_f16(cc[mi][nj*2+1], af[mi], b2, b3);
                }
            }
        }
        sidx++; if (sidx >= 3) sidx = 0;
    }

    // epilogue: out[token] += w * partial (all contributions commute)
    int grp = lane >> 2, tg = lane & 3;
    #pragma unroll
    for (int mi = 0; mi < 4; mi++)
      #pragma unroll
      for (int nf = 0; nf < 8; nf++){
        int r0 = wm*64 + mi*16 + grp;
        int gc = colBase + wn*64 + nf*8 + tg*2;
        if (r0 < rows){
            float w = ws[r0];
            float* o = outp + (size_t)toks[r0]*Hd + gc;
            atomicAdd(o,   w * cc[mi][nf][0]);
            atomicAdd(o+1, w * cc[mi][nf][1]);
        }
        if (r0 + 8 < rows){
            float w = ws[r0+8];
            float* o = outp + (size_t)toks[r0+8]*Hd + gc;
            atomicAdd(o,   w * cc[mi][nf][2]);
            atomicAdd(o+1, w * cc[mi][nf][3]);
        }
      }
}

// ---------------- launch ----------------
extern "C" void kernel_launch(void* const* d_in, const int* in_sizes, int n_in,
                              void* d_out, int out_size)
{
    const float* hidden = (const float*)d_in[0];
    const float* gate_w = (const float*)d_in[1];
    const float* w_gate = (const float*)d_in[2];
    const float* w_up   = (const float*)d_in[3];
    const float* w_down = (const float*)d_in[4];
    float* out = (float*)d_out;

    float* logits_dst;
    if (out_size >= Tn*Hd + Tn*NE) {
        logits_dst = out + (size_t)Tn*Hd;
    } else {
        void* p = nullptr;
        cudaGetSymbolAddress(&p, g_logits_scratch);
        logits_dst = (float*)p;
    }

    void *pwg, *pwu, *pwd;
    cudaGetSymbolAddress(&pwg,  g_wg_h);
    cudaGetSymbolAddress(&pwu,  g_wu_h);
    cudaGetSymbolAddress(&pwd,  g_wd_h);

    // one-time host-side resources (3 side streams — 4 tripped the teardown mem check)
    static cudaStream_t s1 = nullptr, s2 = nullptr, s3 = nullptr;
    static cudaEvent_t evRoot = nullptr, evG2a = nullptr, evG2b = nullptr;
    static cudaEvent_t evQ[4]  = {nullptr,nullptr,nullptr,nullptr};
    static cudaEvent_t evWD[4] = {nullptr,nullptr,nullptr,nullptr};
    static cudaEvent_t evG1[4] = {nullptr,nullptr,nullptr,nullptr};
    static bool inited = false;
    if (!inited){
        cudaStreamCreateWithFlags(&s1, cudaStreamNonBlocking);
        cudaStreamCreateWithFlags(&s2, cudaStreamNonBlocking);
        cudaStreamCreateWithFlags(&s3, cudaStreamNonBlocking);
        cudaEventCreateWithFlags(&evRoot, cudaEventDisableTiming);
        cudaEventCreateWithFlags(&evG2a,  cudaEventDisableTiming);
        cudaEventCreateWithFlags(&evG2b,  cudaEventDisableTiming);
        for (int q = 0; q < 4; q++){
            cudaEventCreateWithFlags(&evQ[q],  cudaEventDisableTiming);
            cudaEventCreateWithFlags(&evWD[q], cudaEventDisableTiming);
            cudaEventCreateWithFlags(&evG1[q], cudaEventDisableTiming);
        }
        cudaFuncSetAttribute(gemm1_kernel, cudaFuncAttributeMaxDynamicSharedMemorySize, SMEM1);
        cudaFuncSetAttribute(gemm2_kernel, cudaFuncAttributeMaxDynamicSharedMemorySize, SMEM2);
        inited = true;
    }

    const int QTR = Id/4;                          // 2048 rows per quarter (per expert)

    // fork: root event on the (capturing) default stream
    zero_kernel<<<1, 32, 0, 0>>>();
    cudaEventRecord(evRoot, 0);
    cudaStreamWaitEvent(s1, evRoot, 0);

    // s1: wg/wu in 4 column-quarters (hidden fp16 produced by the router)
    for (int q = 0; q < 4; q++){
        cvt16_part_kernel<<<2048, 256, 0, s1>>>((const float4*)w_gate, (uint4*)pwg, q*QTR, QTR);
        cvt16_part_kernel<<<2048, 256, 0, s1>>>((const float4*)w_up,   (uint4*)pwu, q*QTR, QTR);
        cudaEventRecord(evQ[q], s1);
    }

    // s2: w_down cvt in K(column)-quarters, AFTER the s1 chain (runs under gemm1)
    cudaStreamWaitEvent(s2, evQ[3], 0);
    for (int q = 0; q < 4; q++){
        cvt16_colpart_kernel<<<2048, 256, 0, s2>>>((const float4*)w_down, (uint4*)pwd,
                                                   NE*Hd, Id/8, q*(Id/4/8), Id/4/8);
        cudaEventRecord(evWD[q], s2);
    }

    // default stream: routing chain (emits g_hid_h) + output zero
    cudaMemsetAsync(d_out, 0, (size_t)Tn*Hd*sizeof(float), 0);
    router_kernel<<<Tn/8, 256, 0, 0>>>(hidden, gate_w, logits_dst);
    prefix_kernel<<<1, 1, 0, 0>>>();
    scatter_kernel<<<Tn/256, 256, 0, 0>>>();

    // gemm1 in 4 column-quarter chunks, each gated on its cvt pair (serial on stream0)
    for (int q = 0; q < 4; q++){
        cudaStreamWaitEvent(0, evQ[q], 0);
        gemm1_kernel<<<dim3(72, QTR/64), 256, SMEM1, 0>>>(q*QTR);
        cudaEventRecord(evG1[q], 0);
    }

    // gemm2 in 2 K-chunks of 4096 (halves the atomic epilogue rounds):
    // chunk0 on s3 gated on gemm1 half (q0,q1) + wd half; chunk1 on s2 gated on the rest
    cudaStreamWaitEvent(s3, evG1[1], 0);
    cudaStreamWaitEvent(s3, evWD[1], 0);
    gemm2_kernel<<<dim3(Hd/128, 72), 128, SMEM2, s3>>>(out, 0*G2_KCHUNK);
    cudaEventRecord(evG2a, s3);

    cudaStreamWaitEvent(s2, evG1[3], 0);
    gemm2_kernel<<<dim3(Hd/128, 72), 128, SMEM2, s2>>>(out, 1*G2_KCHUNK);
    cudaEventRecord(evG2b, s2);

    // join everything back into the capture-origin stream
    cudaStreamWaitEvent(0, evG2a, 0);
    cudaStreamWaitEvent(0, evG2b, 0);
}